// round 8
// baseline (speedup 1.0000x reference)
#include <cuda_runtime.h>
#include <math.h>
#include <stdint.h>

// ---------------- problem constants ----------------
constexpr int kH     = 2048;
constexpr int kL     = 512;    // txt tokens
constexpr int kN     = 2048;   // img tokens
constexpr int kSEQ   = 2560;   // joint sequence
constexpr int kHEADS = 16;
constexpr int kHD    = 128;
constexpr int kMLP   = 8192;

// ---------------- scratch layout (single __device__ array, no allocs) ----
constexpr size_t OFF_SILU = 0;
constexpr size_t OFF_MOD  = OFF_SILU + kH;
constexpr size_t OFF_XN   = OFF_MOD  + (size_t)2 * 6 * kH;
constexpr size_t OFF_QKV  = OFF_XN   + (size_t)kSEQ * kH;
constexpr size_t OFF_Q    = OFF_QKV  + (size_t)kSEQ * 3 * kH;
constexpr size_t OFF_K    = OFF_Q    + (size_t)kHEADS * kSEQ * kHD;
constexpr size_t OFF_VT   = OFF_K    + (size_t)kHEADS * kSEQ * kHD;
constexpr size_t OFF_S    = OFF_VT   + (size_t)kHEADS * kHD * kSEQ;
constexpr size_t OFF_AO   = OFF_S    + (size_t)kHEADS * kSEQ * kSEQ;
constexpr size_t OFF_AOP  = OFF_AO   + (size_t)kSEQ * kH;            // 4 partials
constexpr size_t OFF_RES  = OFF_AOP  + (size_t)4 * kSEQ * kH;
constexpr size_t OFF_H1   = OFF_RES  + (size_t)kSEQ * kH;            // img h1
constexpr size_t OFF_H1T  = OFF_H1   + (size_t)kN * kMLP;            // txt h1
constexpr size_t SCRATCH_TOTAL = OFF_H1T + (size_t)kL * kMLP;

__device__ __align__(256) float g_scratch[SCRATCH_TOTAL];

// round fp32 -> tf32 (rna), result kept in fp32 container
__device__ __forceinline__ float rnd_tf32(float x) {
    uint32_t y;
    asm("cvt.rna.tf32.f32 %0, %1;" : "=r"(y) : "f"(x));
    return __uint_as_float(y);
}

// ---------------- small helper kernels ----------------
__global__ void silu_kernel(const float* __restrict__ vec, float* __restrict__ out) {
    int i = blockIdx.x * blockDim.x + threadIdx.x;
    if (i < kH) {
        float v = vec[i];
        out[i] = v / (1.f + expf(-v));
    }
}

__global__ void adaln_gemv(const float* __restrict__ silu,
                           const float* __restrict__ tw, const float* __restrict__ tb,
                           const float* __restrict__ iw, const float* __restrict__ ib,
                           float* __restrict__ mod) {
    int gw = (blockIdx.x * blockDim.x + threadIdx.x) >> 5;
    int lane = threadIdx.x & 31;
    if (gw >= 2 * 6 * kH) return;
    int set = gw / (6 * kH);
    int o = gw - set * (6 * kH);
    const float* W = (set ? iw : tw) + (size_t)o * kH;
    float s = 0.f;
    for (int i = lane; i < kH; i += 32) s += silu[i] * W[i];
    #pragma unroll
    for (int off = 16; off; off >>= 1) s += __shfl_xor_sync(0xffffffffu, s, off);
    if (lane == 0) mod[(size_t)set * 6 * kH + o] = s + (set ? ib[o] : tb[o]);
}

// out = tf32_round(rms_norm(x, w) * (1 + sc) + sh)
__global__ void norm_mod(const float* __restrict__ x, float* __restrict__ out,
                         const float* __restrict__ w,
                         const float* __restrict__ sh, const float* __restrict__ sc) {
    int row = blockIdx.x;
    const float* xr = x + (size_t)row * kH;
    float* orow = out + (size_t)row * kH;
    int tid = threadIdx.x;
    float ss = 0.f;
    for (int i = tid; i < kH; i += 256) { float v = xr[i]; ss += v * v; }
    __shared__ float sred[8];
    #pragma unroll
    for (int off = 16; off; off >>= 1) ss += __shfl_xor_sync(0xffffffffu, ss, off);
    if ((tid & 31) == 0) sred[tid >> 5] = ss;
    __syncthreads();
    if (tid < 8) {
        float v = sred[tid];
        #pragma unroll
        for (int off = 4; off; off >>= 1) v += __shfl_xor_sync(0xffu, v, off);
        if (tid == 0) sred[0] = v;
    }
    __syncthreads();
    float norm = rsqrtf(sred[0] * (1.f / kH) + 1e-6f);
    for (int i = tid; i < kH; i += 256)
        orow[i] = rnd_tf32(xr[i] * norm * w[i] * (1.f + sc[i]) + sh[i]);
}

// Split qkv, apply RoPE to img q/k, scatter heads; v stored transposed.
__global__ void rope_scatter(const float* __restrict__ qkv, const float* __restrict__ rope,
                             float* __restrict__ q, float* __restrict__ k,
                             float* __restrict__ vt) {
    int gid = blockIdx.x * blockDim.x + threadIdx.x;
    if (gid >= kSEQ * kHEADS * (kHD / 2)) return;
    int j = gid & 63;
    int h = (gid >> 6) & 15;
    int n = gid >> 10;
    int d = j * 2;
    const float qscale = 0.08838834764831845f;
    const float* base = qkv + (size_t)n * 3 * kH;
    float q0 = base[h * kHD + d],          q1 = base[h * kHD + d + 1];
    float k0 = base[kH + h * kHD + d],     k1 = base[kH + h * kHD + d + 1];
    float v0 = base[2 * kH + h * kHD + d], v1 = base[2 * kH + h * kHD + d + 1];
    if (n >= kL) {
        const float* r = rope + (size_t)(n - kL) * kHD + d;
        float c = r[0], s = r[1];
        float t;
        t = q0 * c - q1 * s; q1 = q1 * c + q0 * s; q0 = t;
        t = k0 * c - k1 * s; k1 = k1 * c + k0 * s; k0 = t;
    }
    size_t qi = ((size_t)h * kSEQ + n) * kHD + d;
    q[qi] = rnd_tf32(q0 * qscale); q[qi + 1] = rnd_tf32(q1 * qscale);
    k[qi] = rnd_tf32(k0); k[qi + 1] = rnd_tf32(k1);
    size_t vi = ((size_t)h * kHD + d) * kSEQ + n;
    vt[vi] = rnd_tf32(v0); vt[vi + kSEQ] = rnd_tf32(v1);
}

// Row softmax over 2560 (Q pre-scaled); output tf32-rounded (feeds PV GEMM).
__global__ void softmax_rows(float* __restrict__ S) {
    float* p = S + ((size_t)blockIdx.y * kSEQ + blockIdx.x) * kSEQ;
    int tid = threadIdx.x;
    float vals[10];
    float m = -3.4e38f;
    #pragma unroll
    for (int t = 0; t < 10; t++) { vals[t] = p[tid + t * 256]; m = fmaxf(m, vals[t]); }
    __shared__ float sred[8];
    #pragma unroll
    for (int off = 16; off; off >>= 1) m = fmaxf(m, __shfl_xor_sync(0xffffffffu, m, off));
    if ((tid & 31) == 0) sred[tid >> 5] = m;
    __syncthreads();
    float m2 = sred[0];
    #pragma unroll
    for (int i = 1; i < 8; i++) m2 = fmaxf(m2, sred[i]);
    float sum = 0.f;
    #pragma unroll
    for (int t = 0; t < 10; t++) { vals[t] = __expf(vals[t] - m2); sum += vals[t]; }
    #pragma unroll
    for (int off = 16; off; off >>= 1) sum += __shfl_xor_sync(0xffffffffu, sum, off);
    __syncthreads();
    if ((tid & 31) == 0) sred[tid >> 5] = sum;
    __syncthreads();
    float tot = sred[0] + sred[1] + sred[2] + sred[3] + sred[4] + sred[5] + sred[6] + sred[7];
    float inv = 1.f / tot;
    #pragma unroll
    for (int t = 0; t < 10; t++) p[tid + t * 256] = rnd_tf32(vals[t] * inv);
}

// ao = rnd_tf32(p0 + p1 + p2 + p3)
__global__ void add_pv(const float4* __restrict__ p, float4* __restrict__ ao) {
    const size_t n = (size_t)kSEQ * kH / 4;
    size_t i = (size_t)blockIdx.x * blockDim.x + threadIdx.x;
    if (i >= n) return;
    float4 a = p[i], b = p[i + n], c = p[i + 2 * n], d = p[i + 3 * n];
    float4 o;
    o.x = rnd_tf32(a.x + b.x + c.x + d.x);
    o.y = rnd_tf32(a.y + b.y + c.y + d.y);
    o.z = rnd_tf32(a.z + b.z + c.z + d.z);
    o.w = rnd_tf32(a.w + b.w + c.w + d.w);
    ao[i] = o;
}

// ---------------- pipelined tensor-core TF32 NT GEMM ----------------
// C = A(MxK) * B(NxK)^T, raw fp32 bits into mma.sync (HW tf32 truncation).
// CTA tile 256x128, 256 threads, 8 warps (4M x 2N), warp tile 64x64.
// EPI 0: tf32-rounded store ; EPI 1: bias + tanh-GELU (rounded) ;
// EPI 2: res + gate[col]*(acc+bias), full fp32.
// SPLIT=1: PV split-K mode (y = qblock*4 + kslice, z = head), raw fp32 store.
__device__ __forceinline__ float gelu_tanh(float x) {
    float x3 = x * x * x;
    return 0.5f * x * (1.f + tanhf(0.7978845608028654f * (x + 0.044715f * x3)));
}

__device__ __forceinline__ void mma_tf32(float c[4], const uint32_t a[4],
                                         uint32_t b0, uint32_t b1) {
    asm volatile(
        "mma.sync.aligned.m16n8k8.row.col.f32.tf32.tf32.f32 "
        "{%0,%1,%2,%3}, {%4,%5,%6,%7}, {%8,%9}, {%0,%1,%2,%3};\n"
        : "+f"(c[0]), "+f"(c[1]), "+f"(c[2]), "+f"(c[3])
        : "r"(a[0]), "r"(a[1]), "r"(a[2]), "r"(a[3]), "r"(b0), "r"(b1));
}

__device__ __forceinline__ void cp16(float* smem_dst, const float* gsrc) {
    uint32_t s = (uint32_t)__cvta_generic_to_shared(smem_dst);
    asm volatile("cp.async.cg.shared.global [%0], [%1], 16;\n" :: "r"(s), "l"(gsrc));
}

constexpr int STAGES = 4;
constexpr int PITCH  = 20;
constexpr int BM     = 256;
constexpr int BN     = 128;
constexpr int TILE_A = BM * PITCH;               // words per A stage
constexpr int TILE_B = BN * PITCH;               // words per B stage
constexpr size_t GEMM_SMEM = (size_t)STAGES * (TILE_A + TILE_B) * sizeof(float); // 122880
constexpr int PV_KSLC = 640;
constexpr size_t PV_PART = (size_t)kSEQ * kH;

template <int EPI, int SPLIT>
__global__ __launch_bounds__(256, 1) void gemm_tc(
    const float* __restrict__ A, size_t sA,
    const float* __restrict__ B, size_t sB,
    float* __restrict__ C, size_t sC, int ldc,
    int lda, int ldb,
    const float* __restrict__ bias,
    const float* __restrict__ gate,
    const float* __restrict__ res,
    int M, int N, int K)
{
    const float* Ag;
    const float* Bg;
    int yb;
    if (SPLIT) {
        int head = blockIdx.z, qb = blockIdx.y >> 2, ks = blockIdx.y & 3;
        yb = qb * BM;
        Ag = A + (size_t)head * sA + (size_t)ks * PV_KSLC + (size_t)yb * lda;
        Bg = B + (size_t)head * sB + (size_t)ks * PV_KSLC
               + (size_t)(blockIdx.x * BN) * ldb;
        C += (size_t)ks * PV_PART + (size_t)head * 128;
    } else {
        yb = blockIdx.y * BM;
        Ag = A + (size_t)blockIdx.z * sA + (size_t)yb * lda;
        Bg = B + (size_t)blockIdx.z * sB + (size_t)(blockIdx.x * BN) * ldb;
        C += (size_t)blockIdx.z * sC;
    }
    extern __shared__ float smem[];
    float* As = smem;                        // [STAGES][BM][PITCH]
    float* Bs = smem + STAGES * TILE_A;      // [STAGES][BN][PITCH]

    int tid  = threadIdx.x;
    int warp = tid >> 5, lane = tid & 31;
    int wm = warp >> 1, wn = warp & 1;       // 4 x 2 warp grid, 64x64 tiles
    int qd = lane >> 2, s = lane & 3;

    int frow = tid >> 2;                     // 0..63
    int fc4  = (tid & 3) * 4;

    float acc[4][8][4] = {};
    int nk = K >> 4;

    auto prefetch = [&](int k0i, int st) {
        int kbase = k0i * 16 + fc4;
        float* as = As + st * TILE_A;
        float* bs = Bs + st * TILE_B;
        #pragma unroll
        for (int i = 0; i < 4; i++) {        // A: 256 rows
            int row = i * 64 + frow;
            cp16(as + row * PITCH + fc4, Ag + (size_t)row * lda + kbase);
        }
        #pragma unroll
        for (int i = 0; i < 2; i++) {        // B: 128 rows
            int row = i * 64 + frow;
            cp16(bs + row * PITCH + fc4, Bg + (size_t)row * ldb + kbase);
        }
    };

    #pragma unroll
    for (int st = 0; st < STAGES - 1; st++) {
        if (st < nk) prefetch(st, st);
        asm volatile("cp.async.commit_group;\n");
    }

    for (int k0i = 0; k0i < nk; k0i++) {
        asm volatile("cp.async.wait_group %0;\n" :: "n"(STAGES - 2));
        __syncthreads();

        const float* as = As + (k0i % STAGES) * TILE_A;
        const float* bs = Bs + (k0i % STAGES) * TILE_B;
        #pragma unroll
        for (int kk = 0; kk < 16; kk += 8) {
            uint32_t afr[4][4];
            #pragma unroll
            for (int tm = 0; tm < 4; tm++) {
                int r = wm * 64 + tm * 16 + qd;
                afr[tm][0] = __float_as_uint(as[r * PITCH + kk + s]);
                afr[tm][1] = __float_as_uint(as[(r + 8) * PITCH + kk + s]);
                afr[tm][2] = __float_as_uint(as[r * PITCH + kk + 4 + s]);
                afr[tm][3] = __float_as_uint(as[(r + 8) * PITCH + kk + 4 + s]);
            }
            #pragma unroll
            for (int tn = 0; tn < 8; tn++) {
                int col = wn * 64 + tn * 8 + qd;
                uint32_t b0 = __float_as_uint(bs[col * PITCH + kk + s]);
                uint32_t b1 = __float_as_uint(bs[col * PITCH + kk + 4 + s]);
                #pragma unroll
                for (int tm = 0; tm < 4; tm++)
                    mma_tf32(acc[tm][tn], afr[tm], b0, b1);
            }
        }

        int pf = k0i + STAGES - 1;
        if (pf < nk) prefetch(pf, pf % STAGES);
        asm volatile("cp.async.commit_group;\n");
    }

    int row_base = yb + wm * 64 + qd;
    int col_base = blockIdx.x * BN + wn * 64;
    #pragma unroll
    for (int tm = 0; tm < 4; tm++) {
        #pragma unroll
        for (int tn = 0; tn < 8; tn++) {
            int col = col_base + tn * 8 + 2 * s;
            #pragma unroll
            for (int half = 0; half < 2; half++) {
                int row = row_base + tm * 16 + half * 8;
                float v0 = acc[tm][tn][half * 2 + 0];
                float v1 = acc[tm][tn][half * 2 + 1];
                if (EPI == 0 && !SPLIT) {
                    v0 = rnd_tf32(v0);
                    v1 = rnd_tf32(v1);
                } else if (EPI == 1) {
                    v0 = rnd_tf32(gelu_tanh(v0 + bias[col]));
                    v1 = rnd_tf32(gelu_tanh(v1 + bias[col + 1]));
                } else if (EPI == 2) {
                    if (bias) { v0 += bias[col]; v1 += bias[col + 1]; }
                    const float* rp = res + (size_t)row * ldc + col;
                    v0 = rp[0] + gate[col] * v0;
                    v1 = rp[1] + gate[col + 1] * v1;
                }
                *(float2*)&C[(size_t)row * ldc + col] = make_float2(v0, v1);
            }
        }
    }
}

// ---------------- launch ----------------
extern "C" void kernel_launch(void* const* d_in, const int* in_sizes, int n_in,
                              void* d_out, int out_size) {
    const float* txt           = (const float*)d_in[0];
    const float* img           = (const float*)d_in[1];
    const float* vec           = (const float*)d_in[2];
    const float* rope          = (const float*)d_in[3];
    const float* txt_adaln_w   = (const float*)d_in[4];
    const float* txt_adaln_b   = (const float*)d_in[5];
    const float* txt_adaln_rms = (const float*)d_in[6];
    const float* img_adaln_w   = (const float*)d_in[7];
    const float* img_adaln_b   = (const float*)d_in[8];
    const float* img_adaln_rms = (const float*)d_in[9];
    const float* txt_qkv_w     = (const float*)d_in[10];
    const float* img_qkv_w     = (const float*)d_in[11];
    const float* txt_out_w     = (const float*)d_in[12];
    const float* img_out_w     = (const float*)d_in[13];
    const float* txt_norm2_w   = (const float*)d_in[14];
    const float* img_norm2_w   = (const float*)d_in[15];
    const float* txt_fc1_w     = (const float*)d_in[16];
    const float* txt_fc1_b     = (const float*)d_in[17];
    const float* txt_fc2_w     = (const float*)d_in[18];
    const float* txt_fc2_b     = (const float*)d_in[19];
    const float* img_fc1_w     = (const float*)d_in[20];
    const float* img_fc1_b     = (const float*)d_in[21];
    const float* img_fc2_w     = (const float*)d_in[22];
    const float* img_fc2_b     = (const float*)d_in[23];
    float* out = (float*)d_out;
    (void)in_sizes; (void)n_in; (void)out_size;

    static cudaStream_t s1 = nullptr;
    static cudaEvent_t ev0 = nullptr, ev1 = nullptr, ev2 = nullptr, ev3 = nullptr;
    static bool attr_done = false;
    if (!attr_done) {
        cudaFuncSetAttribute((const void*)gemm_tc<0,0>, cudaFuncAttributeMaxDynamicSharedMemorySize, (int)GEMM_SMEM);
        cudaFuncSetAttribute((const void*)gemm_tc<1,0>, cudaFuncAttributeMaxDynamicSharedMemorySize, (int)GEMM_SMEM);
        cudaFuncSetAttribute((const void*)gemm_tc<2,0>, cudaFuncAttributeMaxDynamicSharedMemorySize, (int)GEMM_SMEM);
        cudaFuncSetAttribute((const void*)gemm_tc<0,1>, cudaFuncAttributeMaxDynamicSharedMemorySize, (int)GEMM_SMEM);
        cudaStreamCreateWithFlags(&s1, cudaStreamNonBlocking);
        cudaEventCreateWithFlags(&ev0, cudaEventDisableTiming);
        cudaEventCreateWithFlags(&ev1, cudaEventDisableTiming);
        cudaEventCreateWithFlags(&ev2, cudaEventDisableTiming);
        cudaEventCreateWithFlags(&ev3, cudaEventDisableTiming);
        attr_done = true;
    }

    float* sc = nullptr;
    cudaGetSymbolAddress((void**)&sc, g_scratch);
    float* silu = sc + OFF_SILU;
    float* mod  = sc + OFF_MOD;
    float* tmod = mod;
    float* imod = mod + 6 * kH;
    float* xn   = sc + OFF_XN;
    float* qkv  = sc + OFF_QKV;
    float* q    = sc + OFF_Q;
    float* k    = sc + OFF_K;
    float* vt   = sc + OFF_VT;
    float* S    = sc + OFF_S;
    float* ao   = sc + OFF_AO;
    float* aop  = sc + OFF_AOP;
    float* res  = sc + OFF_RES;
    float* h1   = sc + OFF_H1;
    float* h1t  = sc + OFF_H1T;

    // adaLN modulation params (main stream)
    silu_kernel<<<8, 256>>>(vec, silu);
    adaln_gemv<<<(2 * 6 * kH) / 8, 256>>>(silu, txt_adaln_w, txt_adaln_b,
                                          img_adaln_w, img_adaln_b, mod);

    // ---- fork: txt qkv chain on s1, img qkv chain on main ----
    cudaEventRecord(ev0, 0);
    cudaStreamWaitEvent(s1, ev0, 0);

    norm_mod<<<kL, 256, 0, s1>>>(txt, xn, txt_adaln_rms, tmod, tmod + kH);
    gemm_tc<0,0><<<dim3(3 * kH / BN, kL / BM), 256, GEMM_SMEM, s1>>>(
        xn, 0, txt_qkv_w, 0, qkv, 0, 3 * kH, kH, kH,
        nullptr, nullptr, nullptr, kL, 3 * kH, kH);
    cudaEventRecord(ev1, s1);

    norm_mod<<<kN, 256>>>(img, xn + (size_t)kL * kH, img_adaln_rms, imod, imod + kH);
    gemm_tc<0,0><<<dim3(3 * kH / BN, kN / BM), 256, GEMM_SMEM>>>(
        xn + (size_t)kL * kH, 0, img_qkv_w, 0, qkv + (size_t)kL * 3 * kH, 0, 3 * kH,
        kH, kH, nullptr, nullptr, nullptr, kN, 3 * kH, kH);
    cudaStreamWaitEvent(0, ev1, 0);

    // RoPE + head scatter
    rope_scatter<<<(kSEQ * kHEADS * 64) / 256, 256>>>(qkv, rope, q, k, vt);

    // joint attention: S = Q K^T, softmax, O = P V (split-K=4)
    gemm_tc<0,0><<<dim3(kSEQ / BN, kSEQ / BM, kHEADS), 256, GEMM_SMEM>>>(
        q, (size_t)kSEQ * kHD, k, (size_t)kSEQ * kHD, S, (size_t)kSEQ * kSEQ, kSEQ,
        kHD, kHD, nullptr, nullptr, nullptr, kSEQ, kSEQ, kHD);
    softmax_rows<<<dim3(kSEQ, kHEADS), 256>>>(S);
    gemm_tc<0,1><<<dim3(1, (kSEQ / BM) * 4, kHEADS), 256, GEMM_SMEM>>>(
        S, (size_t)kSEQ * kSEQ, vt, (size_t)kHD * kSEQ, aop, 0, kH,
        kSEQ, kSEQ, nullptr, nullptr, nullptr, kSEQ, kHD, PV_KSLC);
    add_pv<<<(kSEQ * kH / 4 + 255) / 256, 256>>>((const float4*)aop, (float4*)ao);

    // ---- fork: txt tail on s1, img tail on main ----
    cudaEventRecord(ev2, 0);
    cudaStreamWaitEvent(s1, ev2, 0);

    // txt: out-proj, norm2, fc1, fc2
    gemm_tc<2,0><<<dim3(kH / BN, kL / BM), 256, GEMM_SMEM, s1>>>(
        ao, 0, txt_out_w, 0, res, 0, kH, kH, kH,
        nullptr, tmod + 2 * kH, txt, kL, kH, kH);
    norm_mod<<<kL, 256, 0, s1>>>(res, xn, txt_norm2_w, tmod + 3 * kH, tmod + 4 * kH);
    gemm_tc<1,0><<<dim3(kMLP / BN, kL / BM), 256, GEMM_SMEM, s1>>>(
        xn, 0, txt_fc1_w, 0, h1t, 0, kMLP, kH, kH,
        txt_fc1_b, nullptr, nullptr, kL, kMLP, kH);
    gemm_tc<2,0><<<dim3(kH / BN, kL / BM), 256, GEMM_SMEM, s1>>>(
        h1t, 0, txt_fc2_w, 0, out, 0, kH, kMLP, kMLP,
        txt_fc2_b, tmod + 5 * kH, res, kL, kH, kMLP);
    cudaEventRecord(ev3, s1);

    // img: out-proj, norm2, fc1, fc2
    gemm_tc<2,0><<<dim3(kH / BN, kN / BM), 256, GEMM_SMEM>>>(
        ao + (size_t)kL * kH, 0, img_out_w, 0, res + (size_t)kL * kH, 0, kH, kH, kH,
        nullptr, imod + 2 * kH, img, kN, kH, kH);
    norm_mod<<<kN, 256>>>(res + (size_t)kL * kH, xn + (size_t)kL * kH,
                          img_norm2_w, imod + 3 * kH, imod + 4 * kH);
    gemm_tc<1,0><<<dim3(kMLP / BN, kN / BM), 256, GEMM_SMEM>>>(
        xn + (size_t)kL * kH, 0, img_fc1_w, 0, h1, 0, kMLP, kH, kH,
        img_fc1_b, nullptr, nullptr, kN, kMLP, kH);
    gemm_tc<2,0><<<dim3(kH / BN, kN / BM), 256, GEMM_SMEM>>>(
        h1, 0, img_fc2_w, 0, out + (size_t)kL * kH, 0, kH, kMLP, kMLP,
        img_fc2_b, imod + 5 * kH, res + (size_t)kL * kH, kN, kH, kMLP);

    cudaStreamWaitEvent(0, ev3, 0);
}

// round 9
// speedup vs baseline: 1.8574x; 1.8574x over previous
#include <cuda_runtime.h>
#include <cuda_fp16.h>
#include <math.h>
#include <stdint.h>

// ---------------- problem constants ----------------
constexpr int kH     = 2048;
constexpr int kL     = 512;
constexpr int kN     = 2048;
constexpr int kSEQ   = 2560;
constexpr int kHEADS = 16;
constexpr int kHD    = 128;
constexpr int kMLP   = 8192;

// ---------------- scratch (float + half pools, no allocs) ----------------
constexpr size_t FOFF_SILU = 0;
constexpr size_t FOFF_MOD  = FOFF_SILU + kH;
constexpr size_t FOFF_AOP  = FOFF_MOD + (size_t)2 * 6 * kH;          // 4 partials
constexpr size_t FOFF_RES  = FOFF_AOP + (size_t)4 * kSEQ * kH;
constexpr size_t FTOT      = FOFF_RES + (size_t)kSEQ * kH;

constexpr size_t HOFF_XN   = 0;
constexpr size_t HOFF_QKV  = HOFF_XN  + (size_t)kSEQ * kH;
constexpr size_t HOFF_Q    = HOFF_QKV + (size_t)kSEQ * 3 * kH;
constexpr size_t HOFF_K    = HOFF_Q   + (size_t)kHEADS * kSEQ * kHD;
constexpr size_t HOFF_VT   = HOFF_K   + (size_t)kHEADS * kSEQ * kHD;
constexpr size_t HOFF_S    = HOFF_VT  + (size_t)kHEADS * kHD * kSEQ;
constexpr size_t HOFF_AO   = HOFF_S   + (size_t)kHEADS * kSEQ * kSEQ;
constexpr size_t HOFF_H1   = HOFF_AO  + (size_t)kSEQ * kH;
constexpr size_t HOFF_H1T  = HOFF_H1  + (size_t)kN * kMLP;
constexpr size_t HOFF_WQT  = HOFF_H1T + (size_t)kL * kMLP;           // 3H x H
constexpr size_t HOFF_WQI  = HOFF_WQT + (size_t)3 * kH * kH;
constexpr size_t HOFF_WOT  = HOFF_WQI + (size_t)3 * kH * kH;         // H x H
constexpr size_t HOFF_WOI  = HOFF_WOT + (size_t)kH * kH;
constexpr size_t HOFF_W1T  = HOFF_WOI + (size_t)kH * kH;             // MLP x H
constexpr size_t HOFF_W1I  = HOFF_W1T + (size_t)kMLP * kH;
constexpr size_t HOFF_W2T  = HOFF_W1I + (size_t)kMLP * kH;           // H x MLP
constexpr size_t HOFF_W2I  = HOFF_W2T + (size_t)kH * kMLP;
constexpr size_t HTOT      = HOFF_W2I + (size_t)kH * kMLP;

__device__ __align__(256) float  g_scratch_f[FTOT];
__device__ __align__(256) __half g_scratch_h[HTOT];

// ---------------- small helper kernels ----------------
__global__ void silu_kernel(const float* __restrict__ vec, float* __restrict__ out) {
    int i = blockIdx.x * blockDim.x + threadIdx.x;
    if (i < kH) {
        float v = vec[i];
        out[i] = v / (1.f + expf(-v));
    }
}

__global__ void adaln_gemv(const float* __restrict__ silu,
                           const float* __restrict__ tw, const float* __restrict__ tb,
                           const float* __restrict__ iw, const float* __restrict__ ib,
                           float* __restrict__ mod) {
    int gw = (blockIdx.x * blockDim.x + threadIdx.x) >> 5;
    int lane = threadIdx.x & 31;
    if (gw >= 2 * 6 * kH) return;
    int set = gw / (6 * kH);
    int o = gw - set * (6 * kH);
    const float* W = (set ? iw : tw) + (size_t)o * kH;
    float s = 0.f;
    for (int i = lane; i < kH; i += 32) s += silu[i] * W[i];
    #pragma unroll
    for (int off = 16; off; off >>= 1) s += __shfl_xor_sync(0xffffffffu, s, off);
    if (lane == 0) mod[(size_t)set * 6 * kH + o] = s + (set ? ib[o] : tb[o]);
}

// fp32 -> fp16 conversion (weights), n multiple of 4
__global__ void f2h(const float4* __restrict__ in, __half2* __restrict__ out, int n4) {
    int i = blockIdx.x * blockDim.x + threadIdx.x;
    if (i >= n4) return;
    float4 v = in[i];
    out[2 * i + 0] = __floats2half2_rn(v.x, v.y);
    out[2 * i + 1] = __floats2half2_rn(v.z, v.w);
}

// out(half) = rms_norm(x, w) * (1 + sc) + sh
__global__ void norm_mod(const float* __restrict__ x, __half* __restrict__ out,
                         const float* __restrict__ w,
                         const float* __restrict__ sh, const float* __restrict__ sc) {
    int row = blockIdx.x;
    const float* xr = x + (size_t)row * kH;
    __half* orow = out + (size_t)row * kH;
    int tid = threadIdx.x;
    float ss = 0.f;
    for (int i = tid; i < kH; i += 256) { float v = xr[i]; ss += v * v; }
    __shared__ float sred[8];
    #pragma unroll
    for (int off = 16; off; off >>= 1) ss += __shfl_xor_sync(0xffffffffu, ss, off);
    if ((tid & 31) == 0) sred[tid >> 5] = ss;
    __syncthreads();
    if (tid < 8) {
        float v = sred[tid];
        #pragma unroll
        for (int off = 4; off; off >>= 1) v += __shfl_xor_sync(0xffu, v, off);
        if (tid == 0) sred[0] = v;
    }
    __syncthreads();
    float norm = rsqrtf(sred[0] * (1.f / kH) + 1e-6f);
    for (int i = tid; i < kH; i += 256)
        orow[i] = __float2half_rn(xr[i] * norm * w[i] * (1.f + sc[i]) + sh[i]);
}

// Split qkv (half), RoPE img q/k, scatter heads; v transposed. Q pre-scaled.
__global__ void rope_scatter(const __half* __restrict__ qkv, const float* __restrict__ rope,
                             __half* __restrict__ q, __half* __restrict__ k,
                             __half* __restrict__ vt) {
    int gid = blockIdx.x * blockDim.x + threadIdx.x;
    if (gid >= kSEQ * kHEADS * (kHD / 2)) return;
    int j = gid & 63;
    int h = (gid >> 6) & 15;
    int n = gid >> 10;
    int d = j * 2;
    const float qscale = 0.08838834764831845f;
    const __half* base = qkv + (size_t)n * 3 * kH;
    float2 qv = __half22float2(*(const __half2*)(base + h * kHD + d));
    float2 kv = __half22float2(*(const __half2*)(base + kH + h * kHD + d));
    float2 vv = __half22float2(*(const __half2*)(base + 2 * kH + h * kHD + d));
    float q0 = qv.x, q1 = qv.y, k0 = kv.x, k1 = kv.y;
    if (n >= kL) {
        const float* r = rope + (size_t)(n - kL) * kHD + d;
        float c = r[0], s = r[1];
        float t;
        t = q0 * c - q1 * s; q1 = q1 * c + q0 * s; q0 = t;
        t = k0 * c - k1 * s; k1 = k1 * c + k0 * s; k0 = t;
    }
    size_t qi = ((size_t)h * kSEQ + n) * kHD + d;
    *(__half2*)(q + qi) = __floats2half2_rn(q0 * qscale, q1 * qscale);
    *(__half2*)(k + qi) = __floats2half2_rn(k0, k1);
    size_t vi = ((size_t)h * kHD + d) * kSEQ + n;
    vt[vi] = __float2half_rn(vv.x);
    vt[vi + kSEQ] = __float2half_rn(vv.y);
}

// Row softmax over 2560 (half in/out, fp32 math).
__global__ void softmax_rows(__half* __restrict__ S) {
    __half* p = S + ((size_t)blockIdx.y * kSEQ + blockIdx.x) * kSEQ;
    int tid = threadIdx.x;
    float vals[10];
    float m = -3.4e38f;
    #pragma unroll
    for (int t = 0; t < 10; t++) { vals[t] = __half2float(p[tid + t * 256]); m = fmaxf(m, vals[t]); }
    __shared__ float sred[8];
    #pragma unroll
    for (int off = 16; off; off >>= 1) m = fmaxf(m, __shfl_xor_sync(0xffffffffu, m, off));
    if ((tid & 31) == 0) sred[tid >> 5] = m;
    __syncthreads();
    float m2 = sred[0];
    #pragma unroll
    for (int i = 1; i < 8; i++) m2 = fmaxf(m2, sred[i]);
    float sum = 0.f;
    #pragma unroll
    for (int t = 0; t < 10; t++) { vals[t] = __expf(vals[t] - m2); sum += vals[t]; }
    #pragma unroll
    for (int off = 16; off; off >>= 1) sum += __shfl_xor_sync(0xffffffffu, sum, off);
    __syncthreads();
    if ((tid & 31) == 0) sred[tid >> 5] = sum;
    __syncthreads();
    float tot = sred[0] + sred[1] + sred[2] + sred[3] + sred[4] + sred[5] + sred[6] + sred[7];
    float inv = 1.f / tot;
    #pragma unroll
    for (int t = 0; t < 10; t++) p[tid + t * 256] = __float2half_rn(vals[t] * inv);
}

// ao(half) = p0+p1+p2+p3 (fp32 partials)
__global__ void add_pv(const float4* __restrict__ p, __half2* __restrict__ ao) {
    const size_t n = (size_t)kSEQ * kH / 4;
    size_t i = (size_t)blockIdx.x * blockDim.x + threadIdx.x;
    if (i >= n) return;
    float4 a = p[i], b = p[i + n], c = p[i + 2 * n], d = p[i + 3 * n];
    ao[2 * i + 0] = __floats2half2_rn(a.x + b.x + c.x + d.x, a.y + b.y + c.y + d.y);
    ao[2 * i + 1] = __floats2half2_rn(a.z + b.z + c.z + d.z, a.w + b.w + c.w + d.w);
}

// ---------------- pipelined fp16 tensor-core NT GEMM ----------------
// C = A(MxK) * B(NxK)^T, A/B half, fp32 accumulate (m16n8k16).
// EPI 0: half store ; EPI 1: bias + tanh-GELU -> half ;
// EPI 2: res + gate[col]*(acc+bias) -> float.
// SPLIT=1: PV split-K (y = qblock*4 + kslice, z = head), float partial store.
__device__ __forceinline__ float gelu_tanh(float x) {
    float x3 = x * x * x;
    return 0.5f * x * (1.f + tanhf(0.7978845608028654f * (x + 0.044715f * x3)));
}

__device__ __forceinline__ void mma_f16(float c[4], const uint32_t a[4],
                                        uint32_t b0, uint32_t b1) {
    asm volatile(
        "mma.sync.aligned.m16n8k16.row.col.f32.f16.f16.f32 "
        "{%0,%1,%2,%3}, {%4,%5,%6,%7}, {%8,%9}, {%0,%1,%2,%3};\n"
        : "+f"(c[0]), "+f"(c[1]), "+f"(c[2]), "+f"(c[3])
        : "r"(a[0]), "r"(a[1]), "r"(a[2]), "r"(a[3]), "r"(b0), "r"(b1));
}

__device__ __forceinline__ void cp16(uint32_t* smem_dst, const void* gsrc) {
    uint32_t s = (uint32_t)__cvta_generic_to_shared(smem_dst);
    asm volatile("cp.async.cg.shared.global [%0], [%1], 16;\n" :: "r"(s), "l"(gsrc));
}

constexpr int STAGES = 4;
constexpr int PITCHW = 20;                      // 32-bit words per row (32 halves + pad)
constexpr int TILE_W = 128 * PITCHW;            // words per (operand, stage)
constexpr size_t GEMM_SMEM = (size_t)STAGES * 2 * TILE_W * 4;  // 81920
constexpr int PV_KSLC = 640;
constexpr size_t PV_PART = (size_t)kSEQ * kH;

// CTA tile 128x128, BK=32 halves, 4 warps (2x2), warp tile 64x64, 128 threads.
template <int EPI, int SPLIT>
__global__ __launch_bounds__(128, 2) void gemm_h(
    const __half* __restrict__ A, size_t sA,
    const __half* __restrict__ B, size_t sB,
    void* __restrict__ Cv, size_t sC, int ldc,
    int lda, int ldb,
    const float* __restrict__ bias,
    const float* __restrict__ gate,
    const float* __restrict__ res,
    int M, int N, int K)
{
    const __half* Ag;
    const __half* Bg;
    float* Cf = (float*)Cv;
    __half* Ch = (__half*)Cv;
    int yb;
    if (SPLIT) {
        int head = blockIdx.z, qb = blockIdx.y >> 2, ks = blockIdx.y & 3;
        yb = qb * 128;
        Ag = A + (size_t)head * sA + (size_t)ks * PV_KSLC + (size_t)yb * lda;
        Bg = B + (size_t)head * sB + (size_t)ks * PV_KSLC
               + (size_t)(blockIdx.x * 128) * ldb;
        Cf += (size_t)ks * PV_PART + (size_t)head * 128;
    } else {
        yb = blockIdx.y * 128;
        Ag = A + (size_t)blockIdx.z * sA + (size_t)yb * lda;
        Bg = B + (size_t)blockIdx.z * sB + (size_t)(blockIdx.x * 128) * ldb;
        Cf += (size_t)blockIdx.z * sC;
        Ch += (size_t)blockIdx.z * sC;
    }
    extern __shared__ uint32_t smw[];
    uint32_t* As = smw;                       // [STAGES][128][PITCHW]
    uint32_t* Bs = smw + STAGES * TILE_W;

    int tid  = threadIdx.x;
    int warp = tid >> 5, lane = tid & 31;
    int wm = warp >> 1, wn = warp & 1;        // 2x2 warp grid, 64x64 tiles
    int qd = lane >> 2, s = lane & 3;

    int frow = tid >> 2;                      // 0..31
    int fc4  = (tid & 3) * 4;                 // word chunk within row

    float acc[4][8][4] = {};
    int nk = K >> 5;                          // K in halves, BK=32

    auto prefetch = [&](int k0i, int st) {
        int kbase = k0i * 32 + (tid & 3) * 8; // halves
        uint32_t* as = As + st * TILE_W;
        uint32_t* bs = Bs + st * TILE_W;
        #pragma unroll
        for (int i = 0; i < 4; i++) {
            int row = i * 32 + frow;
            cp16(as + row * PITCHW + fc4, Ag + (size_t)row * lda + kbase);
            cp16(bs + row * PITCHW + fc4, Bg + (size_t)row * ldb + kbase);
        }
    };

    #pragma unroll
    for (int st = 0; st < STAGES - 1; st++) {
        if (st < nk) prefetch(st, st);
        asm volatile("cp.async.commit_group;\n");
    }

    for (int k0i = 0; k0i < nk; k0i++) {
        asm volatile("cp.async.wait_group %0;\n" :: "n"(STAGES - 2));
        __syncthreads();

        const uint32_t* as = As + (k0i % STAGES) * TILE_W;
        const uint32_t* bs = Bs + (k0i % STAGES) * TILE_W;
        #pragma unroll
        for (int kg = 0; kg < 2; kg++) {      // two k16 groups per BK=32
            int kw = kg * 8;                   // word offset of this k16 group
            uint32_t afr[4][4];
            #pragma unroll
            for (int tm = 0; tm < 4; tm++) {
                int r = wm * 64 + tm * 16 + qd;
                afr[tm][0] = as[r * PITCHW + kw + s];
                afr[tm][1] = as[(r + 8) * PITCHW + kw + s];
                afr[tm][2] = as[r * PITCHW + kw + 4 + s];
                afr[tm][3] = as[(r + 8) * PITCHW + kw + 4 + s];
            }
            #pragma unroll
            for (int tn = 0; tn < 8; tn++) {
                int col = wn * 64 + tn * 8 + qd;
                uint32_t b0 = bs[col * PITCHW + kw + s];
                uint32_t b1 = bs[col * PITCHW + kw + 4 + s];
                #pragma unroll
                for (int tm = 0; tm < 4; tm++)
                    mma_f16(acc[tm][tn], afr[tm], b0, b1);
            }
        }

        int pf = k0i + STAGES - 1;
        if (pf < nk) prefetch(pf, pf % STAGES);
        asm volatile("cp.async.commit_group;\n");
    }

    int row_base = yb + wm * 64 + qd;
    int col_base = blockIdx.x * 128 + wn * 64;
    #pragma unroll
    for (int tm = 0; tm < 4; tm++) {
        #pragma unroll
        for (int tn = 0; tn < 8; tn++) {
            int col = col_base + tn * 8 + 2 * s;
            #pragma unroll
            for (int half = 0; half < 2; half++) {
                int row = row_base + tm * 16 + half * 8;
                float v0 = acc[tm][tn][half * 2 + 0];
                float v1 = acc[tm][tn][half * 2 + 1];
                if (SPLIT) {
                    *(float2*)&Cf[(size_t)row * ldc + col] = make_float2(v0, v1);
                } else if (EPI == 0) {
                    *(__half2*)&Ch[(size_t)row * ldc + col] = __floats2half2_rn(v0, v1);
                } else if (EPI == 1) {
                    v0 = gelu_tanh(v0 + bias[col]);
                    v1 = gelu_tanh(v1 + bias[col + 1]);
                    *(__half2*)&Ch[(size_t)row * ldc + col] = __floats2half2_rn(v0, v1);
                } else {
                    if (bias) { v0 += bias[col]; v1 += bias[col + 1]; }
                    const float* rp = res + (size_t)row * ldc + col;
                    v0 = rp[0] + gate[col] * v0;
                    v1 = rp[1] + gate[col + 1] * v1;
                    *(float2*)&Cf[(size_t)row * ldc + col] = make_float2(v0, v1);
                }
            }
        }
    }
}

// ---------------- launch ----------------
extern "C" void kernel_launch(void* const* d_in, const int* in_sizes, int n_in,
                              void* d_out, int out_size) {
    const float* txt           = (const float*)d_in[0];
    const float* img           = (const float*)d_in[1];
    const float* vec           = (const float*)d_in[2];
    const float* rope          = (const float*)d_in[3];
    const float* txt_adaln_w   = (const float*)d_in[4];
    const float* txt_adaln_b   = (const float*)d_in[5];
    const float* txt_adaln_rms = (const float*)d_in[6];
    const float* img_adaln_w   = (const float*)d_in[7];
    const float* img_adaln_b   = (const float*)d_in[8];
    const float* img_adaln_rms = (const float*)d_in[9];
    const float* txt_qkv_w     = (const float*)d_in[10];
    const float* img_qkv_w     = (const float*)d_in[11];
    const float* txt_out_w     = (const float*)d_in[12];
    const float* img_out_w     = (const float*)d_in[13];
    const float* txt_norm2_w   = (const float*)d_in[14];
    const float* img_norm2_w   = (const float*)d_in[15];
    const float* txt_fc1_w     = (const float*)d_in[16];
    const float* txt_fc1_b     = (const float*)d_in[17];
    const float* txt_fc2_w     = (const float*)d_in[18];
    const float* txt_fc2_b     = (const float*)d_in[19];
    const float* img_fc1_w     = (const float*)d_in[20];
    const float* img_fc1_b     = (const float*)d_in[21];
    const float* img_fc2_w     = (const float*)d_in[22];
    const float* img_fc2_b     = (const float*)d_in[23];
    float* out = (float*)d_out;
    (void)in_sizes; (void)n_in; (void)out_size;

    static cudaStream_t s1 = nullptr;
    static cudaEvent_t ev0, ev1, ev2, ev3, ev4;
    static bool init_done = false;
    if (!init_done) {
        cudaFuncSetAttribute((const void*)gemm_h<0,0>, cudaFuncAttributeMaxDynamicSharedMemorySize, (int)GEMM_SMEM);
        cudaFuncSetAttribute((const void*)gemm_h<1,0>, cudaFuncAttributeMaxDynamicSharedMemorySize, (int)GEMM_SMEM);
        cudaFuncSetAttribute((const void*)gemm_h<2,0>, cudaFuncAttributeMaxDynamicSharedMemorySize, (int)GEMM_SMEM);
        cudaFuncSetAttribute((const void*)gemm_h<0,1>, cudaFuncAttributeMaxDynamicSharedMemorySize, (int)GEMM_SMEM);
        cudaStreamCreateWithFlags(&s1, cudaStreamNonBlocking);
        cudaEventCreateWithFlags(&ev0, cudaEventDisableTiming);
        cudaEventCreateWithFlags(&ev1, cudaEventDisableTiming);
        cudaEventCreateWithFlags(&ev2, cudaEventDisableTiming);
        cudaEventCreateWithFlags(&ev3, cudaEventDisableTiming);
        cudaEventCreateWithFlags(&ev4, cudaEventDisableTiming);
        init_done = true;
    }

    float* fs = nullptr;
    __half* hs = nullptr;
    cudaGetSymbolAddress((void**)&fs, g_scratch_f);
    cudaGetSymbolAddress((void**)&hs, g_scratch_h);
    float* silu = fs + FOFF_SILU;
    float* mod  = fs + FOFF_MOD;
    float* tmod = mod;
    float* imod = mod + 6 * kH;
    float* aop  = fs + FOFF_AOP;
    float* res  = fs + FOFF_RES;
    __half* xn  = hs + HOFF_XN;
    __half* qkv = hs + HOFF_QKV;
    __half* q   = hs + HOFF_Q;
    __half* k   = hs + HOFF_K;
    __half* vt  = hs + HOFF_VT;
    __half* S   = hs + HOFF_S;
    __half* ao  = hs + HOFF_AO;
    __half* h1  = hs + HOFF_H1;
    __half* h1t = hs + HOFF_H1T;
    __half* wqt = hs + HOFF_WQT;
    __half* wqi = hs + HOFF_WQI;
    __half* wot = hs + HOFF_WOT;
    __half* woi = hs + HOFF_WOI;
    __half* w1t = hs + HOFF_W1T;
    __half* w1i = hs + HOFF_W1I;
    __half* w2t = hs + HOFF_W2T;
    __half* w2i = hs + HOFF_W2I;

    auto conv = [&](const float* src, __half* dst, size_t n, cudaStream_t st) {
        int n4 = (int)(n / 4);
        f2h<<<(n4 + 255) / 256, 256, 0, st>>>((const float4*)src, (__half2*)dst, n4);
    };

    // adaLN modulation (fp32, main)
    silu_kernel<<<8, 256>>>(vec, silu);
    adaln_gemv<<<(2 * 6 * kH) / 8, 256>>>(silu, txt_adaln_w, txt_adaln_b,
                                          img_adaln_w, img_adaln_b, mod);

    // ---- fork: txt qkv on s1, img qkv on main ----
    cudaEventRecord(ev0, 0);
    cudaStreamWaitEvent(s1, ev0, 0);

    conv(txt_qkv_w, wqt, (size_t)3 * kH * kH, s1);
    norm_mod<<<kL, 256, 0, s1>>>(txt, xn, txt_adaln_rms, tmod, tmod + kH);
    gemm_h<0,0><<<dim3(3 * kH / 128, kL / 128), 128, GEMM_SMEM, s1>>>(
        xn, 0, wqt, 0, qkv, 0, 3 * kH, kH, kH,
        nullptr, nullptr, nullptr, kL, 3 * kH, kH);
    cudaEventRecord(ev1, s1);
    // tail weight conversions on s1 (overlaps attention on main)
    conv(txt_out_w, wot, (size_t)kH * kH, s1);
    conv(img_out_w, woi, (size_t)kH * kH, s1);
    conv(txt_fc1_w, w1t, (size_t)kMLP * kH, s1);
    conv(img_fc1_w, w1i, (size_t)kMLP * kH, s1);
    conv(txt_fc2_w, w2t, (size_t)kH * kMLP, s1);
    conv(img_fc2_w, w2i, (size_t)kH * kMLP, s1);
    cudaEventRecord(ev4, s1);

    conv(img_qkv_w, wqi, (size_t)3 * kH * kH, 0);
    norm_mod<<<kN, 256>>>(img, xn + (size_t)kL * kH, img_adaln_rms, imod, imod + kH);
    gemm_h<0,0><<<dim3(3 * kH / 128, kN / 128), 128, GEMM_SMEM>>>(
        xn + (size_t)kL * kH, 0, wqi, 0, qkv + (size_t)kL * 3 * kH, 0, 3 * kH,
        kH, kH, nullptr, nullptr, nullptr, kN, 3 * kH, kH);
    cudaStreamWaitEvent(0, ev1, 0);

    // RoPE + head scatter
    rope_scatter<<<(kSEQ * kHEADS * 64) / 256, 256>>>(qkv, rope, q, k, vt);

    // joint attention: S = Q K^T, softmax, O = P V (split-K=4)
    gemm_h<0,0><<<dim3(kSEQ / 128, kSEQ / 128, kHEADS), 128, GEMM_SMEM>>>(
        q, (size_t)kSEQ * kHD, k, (size_t)kSEQ * kHD, S, (size_t)kSEQ * kSEQ, kSEQ,
        kHD, kHD, nullptr, nullptr, nullptr, kSEQ, kSEQ, kHD);
    softmax_rows<<<dim3(kSEQ, kHEADS), 256>>>(S);
    gemm_h<0,1><<<dim3(1, (kSEQ / 128) * 4, kHEADS), 128, GEMM_SMEM>>>(
        S, (size_t)kSEQ * kSEQ, vt, (size_t)kHD * kSEQ, aop, 0, kH,
        kSEQ, kSEQ, nullptr, nullptr, nullptr, kSEQ, kHD, PV_KSLC);
    add_pv<<<(kSEQ * kH / 4 + 255) / 256, 256>>>((const float4*)aop, (__half2*)ao);

    // ---- fork: txt tail on s1, img tail on main ----
    cudaEventRecord(ev2, 0);
    cudaStreamWaitEvent(s1, ev2, 0);
    cudaStreamWaitEvent(0, ev4, 0);   // img tail needs weight conversions

    // txt tail
    gemm_h<2,0><<<dim3(kH / 128, kL / 128), 128, GEMM_SMEM, s1>>>(
        ao, 0, wot, 0, res, 0, kH, kH, kH,
        nullptr, tmod + 2 * kH, txt, kL, kH, kH);
    norm_mod<<<kL, 256, 0, s1>>>(res, xn, txt_norm2_w, tmod + 3 * kH, tmod + 4 * kH);
    gemm_h<1,0><<<dim3(kMLP / 128, kL / 128), 128, GEMM_SMEM, s1>>>(
        xn, 0, w1t, 0, h1t, 0, kMLP, kH, kH,
        txt_fc1_b, nullptr, nullptr, kL, kMLP, kH);
    gemm_h<2,0><<<dim3(kH / 128, kL / 128), 128, GEMM_SMEM, s1>>>(
        h1t, 0, w2t, 0, out, 0, kH, kMLP, kMLP,
        txt_fc2_b, tmod + 5 * kH, res, kL, kH, kMLP);
    cudaEventRecord(ev3, s1);

    // img tail
    gemm_h<2,0><<<dim3(kH / 128, kN / 128), 128, GEMM_SMEM>>>(
        ao + (size_t)kL * kH, 0, woi, 0, res + (size_t)kL * kH, 0, kH, kH, kH,
        nullptr, imod + 2 * kH, img, kN, kH, kH);
    norm_mod<<<kN, 256>>>(res + (size_t)kL * kH, xn + (size_t)kL * kH,
                          img_norm2_w, imod + 3 * kH, imod + 4 * kH);
    gemm_h<1,0><<<dim3(kMLP / 128, kN / 128), 128, GEMM_SMEM>>>(
        xn + (size_t)kL * kH, 0, w1i, 0, h1, 0, kMLP, kH, kH,
        img_fc1_b, nullptr, nullptr, kN, kMLP, kH);
    gemm_h<2,0><<<dim3(kH / 128, kN / 128), 128, GEMM_SMEM>>>(
        h1, 0, w2i, 0, out + (size_t)kL * kH, 0, kH, kMLP, kMLP,
        img_fc2_b, imod + 5 * kH, res + (size_t)kL * kH, kN, kH, kMLP);

    cudaStreamWaitEvent(0, ev3, 0);
}

// round 10
// speedup vs baseline: 2.2286x; 1.1999x over previous
#include <cuda_runtime.h>
#include <cuda_fp16.h>
#include <math.h>
#include <stdint.h>

// ---------------- problem constants ----------------
constexpr int kH     = 2048;
constexpr int kL     = 512;
constexpr int kN     = 2048;
constexpr int kSEQ   = 2560;
constexpr int kHEADS = 16;
constexpr int kHD    = 128;
constexpr int kMLP   = 8192;

// ---------------- scratch (float + half pools, no allocs) ----------------
constexpr size_t FOFF_SILU = 0;
constexpr size_t FOFF_MOD  = FOFF_SILU + kH;
constexpr size_t FOFF_AOP  = FOFF_MOD + (size_t)2 * 6 * kH;          // 4 partials
constexpr size_t FOFF_RES  = FOFF_AOP + (size_t)4 * kSEQ * kH;
constexpr size_t FTOT      = FOFF_RES + (size_t)kSEQ * kH;

constexpr size_t HOFF_XN   = 0;
constexpr size_t HOFF_QKV  = HOFF_XN  + (size_t)kSEQ * kH;
constexpr size_t HOFF_Q    = HOFF_QKV + (size_t)kSEQ * 3 * kH;
constexpr size_t HOFF_K    = HOFF_Q   + (size_t)kHEADS * kSEQ * kHD;
constexpr size_t HOFF_VT   = HOFF_K   + (size_t)kHEADS * kSEQ * kHD;
constexpr size_t HOFF_S    = HOFF_VT  + (size_t)kHEADS * kHD * kSEQ;
constexpr size_t HOFF_AO   = HOFF_S   + (size_t)kHEADS * kSEQ * kSEQ;
constexpr size_t HOFF_H1   = HOFF_AO  + (size_t)kSEQ * kH;
constexpr size_t HOFF_H1T  = HOFF_H1  + (size_t)kN * kMLP;
constexpr size_t HOFF_WQT  = HOFF_H1T + (size_t)kL * kMLP;
constexpr size_t HOFF_WQI  = HOFF_WQT + (size_t)3 * kH * kH;
constexpr size_t HOFF_WOT  = HOFF_WQI + (size_t)3 * kH * kH;
constexpr size_t HOFF_WOI  = HOFF_WOT + (size_t)kH * kH;
constexpr size_t HOFF_W1T  = HOFF_WOI + (size_t)kH * kH;
constexpr size_t HOFF_W1I  = HOFF_W1T + (size_t)kMLP * kH;
constexpr size_t HOFF_W2T  = HOFF_W1I + (size_t)kMLP * kH;
constexpr size_t HOFF_W2I  = HOFF_W2T + (size_t)kH * kMLP;
constexpr size_t HTOT      = HOFF_W2I + (size_t)kH * kMLP;

__device__ __align__(256) float  g_scratch_f[FTOT];
__device__ __align__(256) __half g_scratch_h[HTOT];

// ---------------- small helper kernels ----------------
__global__ void silu_kernel(const float* __restrict__ vec, float* __restrict__ out) {
    int i = blockIdx.x * blockDim.x + threadIdx.x;
    if (i < kH) {
        float v = vec[i];
        out[i] = v / (1.f + expf(-v));
    }
}

__global__ void adaln_gemv(const float* __restrict__ silu,
                           const float* __restrict__ tw, const float* __restrict__ tb,
                           const float* __restrict__ iw, const float* __restrict__ ib,
                           float* __restrict__ mod) {
    int gw = (blockIdx.x * blockDim.x + threadIdx.x) >> 5;
    int lane = threadIdx.x & 31;
    if (gw >= 2 * 6 * kH) return;
    int set = gw / (6 * kH);
    int o = gw - set * (6 * kH);
    const float* W = (set ? iw : tw) + (size_t)o * kH;
    float s = 0.f;
    for (int i = lane; i < kH; i += 32) s += silu[i] * W[i];
    #pragma unroll
    for (int off = 16; off; off >>= 1) s += __shfl_xor_sync(0xffffffffu, s, off);
    if (lane == 0) mod[(size_t)set * 6 * kH + o] = s + (set ? ib[o] : tb[o]);
}

__global__ void f2h(const float4* __restrict__ in, __half2* __restrict__ out, int n4) {
    int i = blockIdx.x * blockDim.x + threadIdx.x;
    if (i >= n4) return;
    float4 v = in[i];
    out[2 * i + 0] = __floats2half2_rn(v.x, v.y);
    out[2 * i + 1] = __floats2half2_rn(v.z, v.w);
}

__global__ void norm_mod(const float* __restrict__ x, __half* __restrict__ out,
                         const float* __restrict__ w,
                         const float* __restrict__ sh, const float* __restrict__ sc) {
    int row = blockIdx.x;
    const float* xr = x + (size_t)row * kH;
    __half* orow = out + (size_t)row * kH;
    int tid = threadIdx.x;
    float ss = 0.f;
    for (int i = tid; i < kH; i += 256) { float v = xr[i]; ss += v * v; }
    __shared__ float sred[8];
    #pragma unroll
    for (int off = 16; off; off >>= 1) ss += __shfl_xor_sync(0xffffffffu, ss, off);
    if ((tid & 31) == 0) sred[tid >> 5] = ss;
    __syncthreads();
    if (tid < 8) {
        float v = sred[tid];
        #pragma unroll
        for (int off = 4; off; off >>= 1) v += __shfl_xor_sync(0xffu, v, off);
        if (tid == 0) sred[0] = v;
    }
    __syncthreads();
    float norm = rsqrtf(sred[0] * (1.f / kH) + 1e-6f);
    for (int i = tid; i < kH; i += 256)
        orow[i] = __float2half_rn(xr[i] * norm * w[i] * (1.f + sc[i]) + sh[i]);
}

__global__ void rope_scatter(const __half* __restrict__ qkv, const float* __restrict__ rope,
                             __half* __restrict__ q, __half* __restrict__ k,
                             __half* __restrict__ vt) {
    int gid = blockIdx.x * blockDim.x + threadIdx.x;
    if (gid >= kSEQ * kHEADS * (kHD / 2)) return;
    int j = gid & 63;
    int h = (gid >> 6) & 15;
    int n = gid >> 10;
    int d = j * 2;
    const float qscale = 0.08838834764831845f;
    const __half* base = qkv + (size_t)n * 3 * kH;
    float2 qv = __half22float2(*(const __half2*)(base + h * kHD + d));
    float2 kv = __half22float2(*(const __half2*)(base + kH + h * kHD + d));
    float2 vv = __half22float2(*(const __half2*)(base + 2 * kH + h * kHD + d));
    float q0 = qv.x, q1 = qv.y, k0 = kv.x, k1 = kv.y;
    if (n >= kL) {
        const float* r = rope + (size_t)(n - kL) * kHD + d;
        float c = r[0], s = r[1];
        float t;
        t = q0 * c - q1 * s; q1 = q1 * c + q0 * s; q0 = t;
        t = k0 * c - k1 * s; k1 = k1 * c + k0 * s; k0 = t;
    }
    size_t qi = ((size_t)h * kSEQ + n) * kHD + d;
    *(__half2*)(q + qi) = __floats2half2_rn(q0 * qscale, q1 * qscale);
    *(__half2*)(k + qi) = __floats2half2_rn(k0, k1);
    size_t vi = ((size_t)h * kHD + d) * kSEQ + n;
    vt[vi] = __float2half_rn(vv.x);
    vt[vi + kSEQ] = __float2half_rn(vv.y);
}

// Row softmax over 2560 (half2 vectorized, fp32 math).
__global__ void softmax_rows(__half2* __restrict__ S) {
    __half2* p = S + ((size_t)blockIdx.y * kSEQ + blockIdx.x) * (kSEQ / 2);
    int tid = threadIdx.x;
    float2 vals[5];
    float m = -3.4e38f;
    #pragma unroll
    for (int t = 0; t < 5; t++) {
        vals[t] = __half22float2(p[tid + t * 256]);
        m = fmaxf(m, fmaxf(vals[t].x, vals[t].y));
    }
    __shared__ float sred[8];
    #pragma unroll
    for (int off = 16; off; off >>= 1) m = fmaxf(m, __shfl_xor_sync(0xffffffffu, m, off));
    if ((tid & 31) == 0) sred[tid >> 5] = m;
    __syncthreads();
    float m2 = sred[0];
    #pragma unroll
    for (int i = 1; i < 8; i++) m2 = fmaxf(m2, sred[i]);
    float sum = 0.f;
    #pragma unroll
    for (int t = 0; t < 5; t++) {
        vals[t].x = __expf(vals[t].x - m2);
        vals[t].y = __expf(vals[t].y - m2);
        sum += vals[t].x + vals[t].y;
    }
    #pragma unroll
    for (int off = 16; off; off >>= 1) sum += __shfl_xor_sync(0xffffffffu, sum, off);
    __syncthreads();
    if ((tid & 31) == 0) sred[tid >> 5] = sum;
    __syncthreads();
    float tot = sred[0] + sred[1] + sred[2] + sred[3] + sred[4] + sred[5] + sred[6] + sred[7];
    float inv = 1.f / tot;
    #pragma unroll
    for (int t = 0; t < 5; t++)
        p[tid + t * 256] = __floats2half2_rn(vals[t].x * inv, vals[t].y * inv);
}

__global__ void add_pv(const float4* __restrict__ p, __half2* __restrict__ ao) {
    const size_t n = (size_t)kSEQ * kH / 4;
    size_t i = (size_t)blockIdx.x * blockDim.x + threadIdx.x;
    if (i >= n) return;
    float4 a = p[i], b = p[i + n], c = p[i + 2 * n], d = p[i + 3 * n];
    ao[2 * i + 0] = __floats2half2_rn(a.x + b.x + c.x + d.x, a.y + b.y + c.y + d.y);
    ao[2 * i + 1] = __floats2half2_rn(a.z + b.z + c.z + d.z, a.w + b.w + c.w + d.w);
}

// ---------------- pipelined fp16 tensor-core NT GEMM (ldmatrix) ----------
__device__ __forceinline__ float gelu_tanh(float x) {
    float x3 = x * x * x;
    return 0.5f * x * (1.f + tanhf(0.7978845608028654f * (x + 0.044715f * x3)));
}

__device__ __forceinline__ void mma_f16(float c[4], const uint32_t a[4],
                                        uint32_t b0, uint32_t b1) {
    asm volatile(
        "mma.sync.aligned.m16n8k16.row.col.f32.f16.f16.f32 "
        "{%0,%1,%2,%3}, {%4,%5,%6,%7}, {%8,%9}, {%0,%1,%2,%3};\n"
        : "+f"(c[0]), "+f"(c[1]), "+f"(c[2]), "+f"(c[3])
        : "r"(a[0]), "r"(a[1]), "r"(a[2]), "r"(a[3]), "r"(b0), "r"(b1));
}

__device__ __forceinline__ void ldsm4(uint32_t& r0, uint32_t& r1, uint32_t& r2,
                                      uint32_t& r3, const uint32_t* p) {
    uint32_t a = (uint32_t)__cvta_generic_to_shared(p);
    asm volatile("ldmatrix.sync.aligned.m8n8.x4.shared.b16 {%0,%1,%2,%3}, [%4];\n"
                 : "=r"(r0), "=r"(r1), "=r"(r2), "=r"(r3) : "r"(a));
}

__device__ __forceinline__ void cp16(uint32_t* smem_dst, const void* gsrc) {
    uint32_t s = (uint32_t)__cvta_generic_to_shared(smem_dst);
    asm volatile("cp.async.cg.shared.global [%0], [%1], 16;\n" :: "r"(s), "l"(gsrc));
}

constexpr int STAGES = 4;
constexpr int PITCHW = 20;                      // 32-bit words per row
constexpr int TILE_W = 128 * PITCHW;
constexpr size_t GEMM_SMEM = (size_t)STAGES * 2 * TILE_W * 4;  // 81920
constexpr int PV_KSLC = 640;
constexpr size_t PV_PART = (size_t)kSEQ * kH;

// CTA 128x128, BK=32 halves, 4 warps (2x2), warp tile 64x64, 128 threads.
template <int EPI, int SPLIT>
__global__ __launch_bounds__(128, 2) void gemm_h(
    const __half* __restrict__ A, size_t sA,
    const __half* __restrict__ B, size_t sB,
    void* __restrict__ Cv, size_t sC, int ldc,
    int lda, int ldb,
    const float* __restrict__ bias,
    const float* __restrict__ gate,
    const float* __restrict__ res,
    int M, int N, int K)
{
    const __half* Ag;
    const __half* Bg;
    float* Cf = (float*)Cv;
    __half* Ch = (__half*)Cv;
    int yb;
    if (SPLIT) {
        int head = blockIdx.z, qb = blockIdx.y >> 2, ks = blockIdx.y & 3;
        yb = qb * 128;
        Ag = A + (size_t)head * sA + (size_t)ks * PV_KSLC + (size_t)yb * lda;
        Bg = B + (size_t)head * sB + (size_t)ks * PV_KSLC
               + (size_t)(blockIdx.x * 128) * ldb;
        Cf += (size_t)ks * PV_PART + (size_t)head * 128;
    } else {
        yb = blockIdx.y * 128;
        Ag = A + (size_t)blockIdx.z * sA + (size_t)yb * lda;
        Bg = B + (size_t)blockIdx.z * sB + (size_t)(blockIdx.x * 128) * ldb;
        Cf += (size_t)blockIdx.z * sC;
        Ch += (size_t)blockIdx.z * sC;
    }
    extern __shared__ uint32_t smw[];
    uint32_t* As = smw;
    uint32_t* Bs = smw + STAGES * TILE_W;

    int tid  = threadIdx.x;
    int warp = tid >> 5, lane = tid & 31;
    int wm = warp >> 1, wn = warp & 1;
    int qd = lane >> 2, s = lane & 3;

    int frow = tid >> 2;
    int fc4  = (tid & 3) * 4;

    // ldmatrix per-lane coords
    // A x4: [r0-7,k0][r8-15,k0][r0-7,k8][r8-15,k8]
    int a_row = wm * 64 + ((lane >> 3) & 1) * 8 + (lane & 7);
    int a_kw  = (lane >> 4) * 4;
    // B x4 (per n-block pair): [n0-7,k0][n0-7,k8][n8-15,k0][n8-15,k8]
    int b_row = wn * 64 + (lane >> 4) * 8 + (lane & 7);
    int b_kw  = ((lane >> 3) & 1) * 4;

    float acc[4][8][4] = {};
    int nk = K >> 5;

    auto prefetch = [&](int k0i, int st) {
        int kbase = k0i * 32 + (tid & 3) * 8;
        uint32_t* as = As + st * TILE_W;
        uint32_t* bs = Bs + st * TILE_W;
        #pragma unroll
        for (int i = 0; i < 4; i++) {
            int row = i * 32 + frow;
            cp16(as + row * PITCHW + fc4, Ag + (size_t)row * lda + kbase);
            cp16(bs + row * PITCHW + fc4, Bg + (size_t)row * ldb + kbase);
        }
    };

    #pragma unroll
    for (int st = 0; st < STAGES - 1; st++) {
        if (st < nk) prefetch(st, st);
        asm volatile("cp.async.commit_group;\n");
    }

    for (int k0i = 0; k0i < nk; k0i++) {
        asm volatile("cp.async.wait_group %0;\n" :: "n"(STAGES - 2));
        __syncthreads();

        const uint32_t* as = As + (k0i % STAGES) * TILE_W;
        const uint32_t* bs = Bs + (k0i % STAGES) * TILE_W;
        #pragma unroll
        for (int kg = 0; kg < 2; kg++) {
            int kw = kg * 8;
            uint32_t afr[4][4];
            #pragma unroll
            for (int tm = 0; tm < 4; tm++)
                ldsm4(afr[tm][0], afr[tm][1], afr[tm][2], afr[tm][3],
                      as + (a_row + tm * 16) * PITCHW + kw + a_kw);
            uint32_t bfr[8][2];
            #pragma unroll
            for (int tp = 0; tp < 4; tp++)
                ldsm4(bfr[2 * tp][0], bfr[2 * tp][1], bfr[2 * tp + 1][0], bfr[2 * tp + 1][1],
                      bs + (b_row + tp * 16) * PITCHW + kw + b_kw);
            #pragma unroll
            for (int tn = 0; tn < 8; tn++)
                #pragma unroll
                for (int tm = 0; tm < 4; tm++)
                    mma_f16(acc[tm][tn], afr[tm], bfr[tn][0], bfr[tn][1]);
        }

        int pf = k0i + STAGES - 1;
        if (pf < nk) prefetch(pf, pf % STAGES);
        asm volatile("cp.async.commit_group;\n");
    }

    int row_base = yb + wm * 64 + qd;
    int col_base = blockIdx.x * 128 + wn * 64;
    #pragma unroll
    for (int tm = 0; tm < 4; tm++) {
        #pragma unroll
        for (int tn = 0; tn < 8; tn++) {
            int col = col_base + tn * 8 + 2 * s;
            #pragma unroll
            for (int half = 0; half < 2; half++) {
                int row = row_base + tm * 16 + half * 8;
                float v0 = acc[tm][tn][half * 2 + 0];
                float v1 = acc[tm][tn][half * 2 + 1];
                if (SPLIT) {
                    *(float2*)&Cf[(size_t)row * ldc + col] = make_float2(v0, v1);
                } else if (EPI == 0) {
                    *(__half2*)&Ch[(size_t)row * ldc + col] = __floats2half2_rn(v0, v1);
                } else if (EPI == 1) {
                    v0 = gelu_tanh(v0 + bias[col]);
                    v1 = gelu_tanh(v1 + bias[col + 1]);
                    *(__half2*)&Ch[(size_t)row * ldc + col] = __floats2half2_rn(v0, v1);
                } else {
                    if (bias) { v0 += bias[col]; v1 += bias[col + 1]; }
                    const float* rp = res + (size_t)row * ldc + col;
                    v0 = rp[0] + gate[col] * v0;
                    v1 = rp[1] + gate[col + 1] * v1;
                    *(float2*)&Cf[(size_t)row * ldc + col] = make_float2(v0, v1);
                }
            }
        }
    }
}

// ---------------- launch ----------------
extern "C" void kernel_launch(void* const* d_in, const int* in_sizes, int n_in,
                              void* d_out, int out_size) {
    const float* txt           = (const float*)d_in[0];
    const float* img           = (const float*)d_in[1];
    const float* vec           = (const float*)d_in[2];
    const float* rope          = (const float*)d_in[3];
    const float* txt_adaln_w   = (const float*)d_in[4];
    const float* txt_adaln_b   = (const float*)d_in[5];
    const float* txt_adaln_rms = (const float*)d_in[6];
    const float* img_adaln_w   = (const float*)d_in[7];
    const float* img_adaln_b   = (const float*)d_in[8];
    const float* img_adaln_rms = (const float*)d_in[9];
    const float* txt_qkv_w     = (const float*)d_in[10];
    const float* img_qkv_w     = (const float*)d_in[11];
    const float* txt_out_w     = (const float*)d_in[12];
    const float* img_out_w     = (const float*)d_in[13];
    const float* txt_norm2_w   = (const float*)d_in[14];
    const float* img_norm2_w   = (const float*)d_in[15];
    const float* txt_fc1_w     = (const float*)d_in[16];
    const float* txt_fc1_b     = (const float*)d_in[17];
    const float* txt_fc2_w     = (const float*)d_in[18];
    const float* txt_fc2_b     = (const float*)d_in[19];
    const float* img_fc1_w     = (const float*)d_in[20];
    const float* img_fc1_b     = (const float*)d_in[21];
    const float* img_fc2_w     = (const float*)d_in[22];
    const float* img_fc2_b     = (const float*)d_in[23];
    float* out = (float*)d_out;
    (void)in_sizes; (void)n_in; (void)out_size;

    static cudaStream_t s1 = nullptr;
    static cudaEvent_t ev0, ev1, ev2, ev3, ev4;
    static bool init_done = false;
    if (!init_done) {
        cudaFuncSetAttribute((const void*)gemm_h<0,0>, cudaFuncAttributeMaxDynamicSharedMemorySize, (int)GEMM_SMEM);
        cudaFuncSetAttribute((const void*)gemm_h<1,0>, cudaFuncAttributeMaxDynamicSharedMemorySize, (int)GEMM_SMEM);
        cudaFuncSetAttribute((const void*)gemm_h<2,0>, cudaFuncAttributeMaxDynamicSharedMemorySize, (int)GEMM_SMEM);
        cudaFuncSetAttribute((const void*)gemm_h<0,1>, cudaFuncAttributeMaxDynamicSharedMemorySize, (int)GEMM_SMEM);
        cudaStreamCreateWithFlags(&s1, cudaStreamNonBlocking);
        cudaEventCreateWithFlags(&ev0, cudaEventDisableTiming);
        cudaEventCreateWithFlags(&ev1, cudaEventDisableTiming);
        cudaEventCreateWithFlags(&ev2, cudaEventDisableTiming);
        cudaEventCreateWithFlags(&ev3, cudaEventDisableTiming);
        cudaEventCreateWithFlags(&ev4, cudaEventDisableTiming);
        init_done = true;
    }

    float* fs = nullptr;
    __half* hs = nullptr;
    cudaGetSymbolAddress((void**)&fs, g_scratch_f);
    cudaGetSymbolAddress((void**)&hs, g_scratch_h);
    float* silu = fs + FOFF_SILU;
    float* mod  = fs + FOFF_MOD;
    float* tmod = mod;
    float* imod = mod + 6 * kH;
    float* aop  = fs + FOFF_AOP;
    float* res  = fs + FOFF_RES;
    __half* xn  = hs + HOFF_XN;
    __half* qkv = hs + HOFF_QKV;
    __half* q   = hs + HOFF_Q;
    __half* k   = hs + HOFF_K;
    __half* vt  = hs + HOFF_VT;
    __half* S   = hs + HOFF_S;
    __half* ao  = hs + HOFF_AO;
    __half* h1  = hs + HOFF_H1;
    __half* h1t = hs + HOFF_H1T;
    __half* wqt = hs + HOFF_WQT;
    __half* wqi = hs + HOFF_WQI;
    __half* wot = hs + HOFF_WOT;
    __half* woi = hs + HOFF_WOI;
    __half* w1t = hs + HOFF_W1T;
    __half* w1i = hs + HOFF_W1I;
    __half* w2t = hs + HOFF_W2T;
    __half* w2i = hs + HOFF_W2I;

    auto conv = [&](const float* src, __half* dst, size_t n, cudaStream_t st) {
        int n4 = (int)(n / 4);
        f2h<<<(n4 + 255) / 256, 256, 0, st>>>((const float4*)src, (__half2*)dst, n4);
    };

    // adaLN modulation (fp32, main)
    silu_kernel<<<8, 256>>>(vec, silu);
    adaln_gemv<<<(2 * 6 * kH) / 8, 256>>>(silu, txt_adaln_w, txt_adaln_b,
                                          img_adaln_w, img_adaln_b, mod);

    // ---- fork: txt qkv on s1, img qkv on main ----
    cudaEventRecord(ev0, 0);
    cudaStreamWaitEvent(s1, ev0, 0);

    conv(txt_qkv_w, wqt, (size_t)3 * kH * kH, s1);
    norm_mod<<<kL, 256, 0, s1>>>(txt, xn, txt_adaln_rms, tmod, tmod + kH);
    gemm_h<0,0><<<dim3(3 * kH / 128, kL / 128), 128, GEMM_SMEM, s1>>>(
        xn, 0, wqt, 0, qkv, 0, 3 * kH, kH, kH,
        nullptr, nullptr, nullptr, kL, 3 * kH, kH);
    cudaEventRecord(ev1, s1);
    conv(txt_out_w, wot, (size_t)kH * kH, s1);
    conv(img_out_w, woi, (size_t)kH * kH, s1);
    conv(txt_fc1_w, w1t, (size_t)kMLP * kH, s1);
    conv(img_fc1_w, w1i, (size_t)kMLP * kH, s1);
    conv(txt_fc2_w, w2t, (size_t)kH * kMLP, s1);
    conv(img_fc2_w, w2i, (size_t)kH * kMLP, s1);
    cudaEventRecord(ev4, s1);

    conv(img_qkv_w, wqi, (size_t)3 * kH * kH, 0);
    norm_mod<<<kN, 256>>>(img, xn + (size_t)kL * kH, img_adaln_rms, imod, imod + kH);
    gemm_h<0,0><<<dim3(3 * kH / 128, kN / 128), 128, GEMM_SMEM>>>(
        xn + (size_t)kL * kH, 0, wqi, 0, qkv + (size_t)kL * 3 * kH, 0, 3 * kH,
        kH, kH, nullptr, nullptr, nullptr, kN, 3 * kH, kH);
    cudaStreamWaitEvent(0, ev1, 0);

    // RoPE + head scatter
    rope_scatter<<<(kSEQ * kHEADS * 64) / 256, 256>>>(qkv, rope, q, k, vt);

    // joint attention: S = Q K^T, softmax, O = P V (split-K=4)
    gemm_h<0,0><<<dim3(kSEQ / 128, kSEQ / 128, kHEADS), 128, GEMM_SMEM>>>(
        q, (size_t)kSEQ * kHD, k, (size_t)kSEQ * kHD, S, (size_t)kSEQ * kSEQ, kSEQ,
        kHD, kHD, nullptr, nullptr, nullptr, kSEQ, kSEQ, kHD);
    softmax_rows<<<dim3(kSEQ, kHEADS), 256>>>((__half2*)S);
    gemm_h<0,1><<<dim3(1, (kSEQ / 128) * 4, kHEADS), 128, GEMM_SMEM>>>(
        S, (size_t)kSEQ * kSEQ, vt, (size_t)kHD * kSEQ, aop, 0, kH,
        kSEQ, kSEQ, nullptr, nullptr, nullptr, kSEQ, kHD, PV_KSLC);
    add_pv<<<(kSEQ * kH / 4 + 255) / 256, 256>>>((const float4*)aop, (__half2*)ao);

    // ---- fork: txt tail on s1, img tail on main ----
    cudaEventRecord(ev2, 0);
    cudaStreamWaitEvent(s1, ev2, 0);
    cudaStreamWaitEvent(0, ev4, 0);

    // txt tail
    gemm_h<2,0><<<dim3(kH / 128, kL / 128), 128, GEMM_SMEM, s1>>>(
        ao, 0, wot, 0, res, 0, kH, kH, kH,
        nullptr, tmod + 2 * kH, txt, kL, kH, kH);
    norm_mod<<<kL, 256, 0, s1>>>(res, xn, txt_norm2_w, tmod + 3 * kH, tmod + 4 * kH);
    gemm_h<1,0><<<dim3(kMLP / 128, kL / 128), 128, GEMM_SMEM, s1>>>(
        xn, 0, w1t, 0, h1t, 0, kMLP, kH, kH,
        txt_fc1_b, nullptr, nullptr, kL, kMLP, kH);
    gemm_h<2,0><<<dim3(kH / 128, kL / 128), 128, GEMM_SMEM, s1>>>(
        h1t, 0, w2t, 0, out, 0, kH, kMLP, kMLP,
        txt_fc2_b, tmod + 5 * kH, res, kL, kH, kMLP);
    cudaEventRecord(ev3, s1);

    // img tail
    gemm_h<2,0><<<dim3(kH / 128, kN / 128), 128, GEMM_SMEM>>>(
        ao + (size_t)kL * kH, 0, woi, 0, res + (size_t)kL * kH, 0, kH, kH, kH,
        nullptr, imod + 2 * kH, img, kN, kH, kH);
    norm_mod<<<kN, 256>>>(res + (size_t)kL * kH, xn + (size_t)kL * kH,
                          img_norm2_w, imod + 3 * kH, imod + 4 * kH);
    gemm_h<1,0><<<dim3(kMLP / 128, kN / 128), 128, GEMM_SMEM>>>(
        xn + (size_t)kL * kH, 0, w1i, 0, h1, 0, kMLP, kH, kH,
        img_fc1_b, nullptr, nullptr, kN, kMLP, kH);
    gemm_h<2,0><<<dim3(kH / 128, kN / 128), 128, GEMM_SMEM>>>(
        h1, 0, w2i, 0, out + (size_t)kL * kH, 0, kH, kMLP, kMLP,
        img_fc2_b, imod + 5 * kH, res + (size_t)kL * kH, kN, kH, kMLP);

    cudaStreamWaitEvent(0, ev3, 0);
}

// round 12
// speedup vs baseline: 2.3973x; 1.0757x over previous
#include <cuda_runtime.h>
#include <cuda_fp16.h>
#include <math.h>
#include <stdint.h>

// ---------------- problem constants ----------------
constexpr int kH     = 2048;
constexpr int kL     = 512;
constexpr int kN     = 2048;
constexpr int kSEQ   = 2560;
constexpr int kHEADS = 16;
constexpr int kHD    = 128;
constexpr int kMLP   = 8192;

// ---------------- scratch (float + half pools, no allocs) ----------------
constexpr size_t FOFF_SILU = 0;
constexpr size_t FOFF_MOD  = FOFF_SILU + kH;
constexpr size_t FOFF_RES  = FOFF_MOD + (size_t)2 * 6 * kH;
constexpr size_t FTOT      = FOFF_RES + (size_t)kSEQ * kH;

constexpr size_t HOFF_XN   = 0;
constexpr size_t HOFF_QKV  = HOFF_XN  + (size_t)kSEQ * kH;
constexpr size_t HOFF_Q    = HOFF_QKV + (size_t)kSEQ * 3 * kH;
constexpr size_t HOFF_K    = HOFF_Q   + (size_t)kHEADS * kSEQ * kHD;
constexpr size_t HOFF_VT   = HOFF_K   + (size_t)kHEADS * kSEQ * kHD;
constexpr size_t HOFF_AO   = HOFF_VT  + (size_t)kHEADS * kHD * kSEQ;
constexpr size_t HOFF_H1   = HOFF_AO  + (size_t)kSEQ * kH;
constexpr size_t HOFF_H1T  = HOFF_H1  + (size_t)kN * kMLP;
constexpr size_t HOFF_WQT  = HOFF_H1T + (size_t)kL * kMLP;
constexpr size_t HOFF_WQI  = HOFF_WQT + (size_t)3 * kH * kH;
constexpr size_t HOFF_WOT  = HOFF_WQI + (size_t)3 * kH * kH;
constexpr size_t HOFF_WOI  = HOFF_WOT + (size_t)kH * kH;
constexpr size_t HOFF_W1T  = HOFF_WOI + (size_t)kH * kH;
constexpr size_t HOFF_W1I  = HOFF_W1T + (size_t)kMLP * kH;
constexpr size_t HOFF_W2T  = HOFF_W1I + (size_t)kMLP * kH;
constexpr size_t HOFF_W2I  = HOFF_W2T + (size_t)kH * kMLP;
constexpr size_t HTOT      = HOFF_W2I + (size_t)kH * kMLP;

__device__ __align__(256) float  g_scratch_f[FTOT];
__device__ __align__(256) __half g_scratch_h[HTOT];

// ---------------- small helper kernels ----------------
__global__ void silu_kernel(const float* __restrict__ vec, float* __restrict__ out) {
    int i = blockIdx.x * blockDim.x + threadIdx.x;
    if (i < kH) {
        float v = vec[i];
        out[i] = v / (1.f + expf(-v));
    }
}

__global__ void adaln_gemv(const float* __restrict__ silu,
                           const float* __restrict__ tw, const float* __restrict__ tb,
                           const float* __restrict__ iw, const float* __restrict__ ib,
                           float* __restrict__ mod) {
    int gw = (blockIdx.x * blockDim.x + threadIdx.x) >> 5;
    int lane = threadIdx.x & 31;
    if (gw >= 2 * 6 * kH) return;
    int set = gw / (6 * kH);
    int o = gw - set * (6 * kH);
    const float* W = (set ? iw : tw) + (size_t)o * kH;
    float s = 0.f;
    for (int i = lane; i < kH; i += 32) s += silu[i] * W[i];
    #pragma unroll
    for (int off = 16; off; off >>= 1) s += __shfl_xor_sync(0xffffffffu, s, off);
    if (lane == 0) mod[(size_t)set * 6 * kH + o] = s + (set ? ib[o] : tb[o]);
}

__global__ void f2h(const float4* __restrict__ in, __half2* __restrict__ out, int n4) {
    int i = blockIdx.x * blockDim.x + threadIdx.x;
    if (i >= n4) return;
    float4 v = in[i];
    out[2 * i + 0] = __floats2half2_rn(v.x, v.y);
    out[2 * i + 1] = __floats2half2_rn(v.z, v.w);
}

__global__ void norm_mod(const float* __restrict__ x, __half* __restrict__ out,
                         const float* __restrict__ w,
                         const float* __restrict__ sh, const float* __restrict__ sc) {
    int row = blockIdx.x;
    const float* xr = x + (size_t)row * kH;
    __half* orow = out + (size_t)row * kH;
    int tid = threadIdx.x;
    float ss = 0.f;
    for (int i = tid; i < kH; i += 256) { float v = xr[i]; ss += v * v; }
    __shared__ float sred[8];
    #pragma unroll
    for (int off = 16; off; off >>= 1) ss += __shfl_xor_sync(0xffffffffu, ss, off);
    if ((tid & 31) == 0) sred[tid >> 5] = ss;
    __syncthreads();
    if (tid < 8) {
        float v = sred[tid];
        #pragma unroll
        for (int off = 4; off; off >>= 1) v += __shfl_xor_sync(0xffu, v, off);
        if (tid == 0) sred[0] = v;
    }
    __syncthreads();
    float norm = rsqrtf(sred[0] * (1.f / kH) + 1e-6f);
    for (int i = tid; i < kH; i += 256)
        orow[i] = __float2half_rn(xr[i] * norm * w[i] * (1.f + sc[i]) + sh[i]);
}

__global__ void rope_scatter(const __half* __restrict__ qkv, const float* __restrict__ rope,
                             __half* __restrict__ q, __half* __restrict__ k,
                             __half* __restrict__ vt) {
    int gid = blockIdx.x * blockDim.x + threadIdx.x;
    if (gid >= kSEQ * kHEADS * (kHD / 2)) return;
    int j = gid & 63;
    int h = (gid >> 6) & 15;
    int n = gid >> 10;
    int d = j * 2;
    const float qscale = 0.08838834764831845f;
    const __half* base = qkv + (size_t)n * 3 * kH;
    float2 qv = __half22float2(*(const __half2*)(base + h * kHD + d));
    float2 kv = __half22float2(*(const __half2*)(base + kH + h * kHD + d));
    float2 vv = __half22float2(*(const __half2*)(base + 2 * kH + h * kHD + d));
    float q0 = qv.x, q1 = qv.y, k0 = kv.x, k1 = kv.y;
    if (n >= kL) {
        const float* r = rope + (size_t)(n - kL) * kHD + d;
        float c = r[0], s = r[1];
        float t;
        t = q0 * c - q1 * s; q1 = q1 * c + q0 * s; q0 = t;
        t = k0 * c - k1 * s; k1 = k1 * c + k0 * s; k0 = t;
    }
    size_t qi = ((size_t)h * kSEQ + n) * kHD + d;
    *(__half2*)(q + qi) = __floats2half2_rn(q0 * qscale, q1 * qscale);
    *(__half2*)(k + qi) = __floats2half2_rn(k0, k1);
    size_t vi = ((size_t)h * kHD + d) * kSEQ + n;
    vt[vi] = __float2half_rn(vv.x);
    vt[vi + kSEQ] = __float2half_rn(vv.y);
}

// ---------------- shared mma/ldmatrix/cp.async helpers ----------------
__device__ __forceinline__ float gelu_tanh(float x) {
    float x3 = x * x * x;
    return 0.5f * x * (1.f + tanhf(0.7978845608028654f * (x + 0.044715f * x3)));
}

// pack two fp32 into a half2 register image (lo -> low 16 bits)
__device__ __forceinline__ uint32_t pack_half2(float lo, float hi) {
    uint32_t r;
    asm("cvt.rn.f16x2.f32 %0, %1, %2;" : "=r"(r) : "f"(hi), "f"(lo));
    return r;
}

__device__ __forceinline__ void mma_f16(float c[4], const uint32_t a[4],
                                        uint32_t b0, uint32_t b1) {
    asm volatile(
        "mma.sync.aligned.m16n8k16.row.col.f32.f16.f16.f32 "
        "{%0,%1,%2,%3}, {%4,%5,%6,%7}, {%8,%9}, {%0,%1,%2,%3};\n"
        : "+f"(c[0]), "+f"(c[1]), "+f"(c[2]), "+f"(c[3])
        : "r"(a[0]), "r"(a[1]), "r"(a[2]), "r"(a[3]), "r"(b0), "r"(b1));
}

__device__ __forceinline__ void ldsm4(uint32_t& r0, uint32_t& r1, uint32_t& r2,
                                      uint32_t& r3, const uint32_t* p) {
    uint32_t a = (uint32_t)__cvta_generic_to_shared(p);
    asm volatile("ldmatrix.sync.aligned.m8n8.x4.shared.b16 {%0,%1,%2,%3}, [%4];\n"
                 : "=r"(r0), "=r"(r1), "=r"(r2), "=r"(r3) : "r"(a));
}

__device__ __forceinline__ void cp16(uint32_t* smem_dst, const void* gsrc) {
    uint32_t s = (uint32_t)__cvta_generic_to_shared(smem_dst);
    asm volatile("cp.async.cg.shared.global [%0], [%1], 16;\n" :: "r"(s), "l"(gsrc));
}

// ================= fused flash attention ==================================
// grid (20 qblocks, 16 heads), 256 threads / 8 warps; warp owns 16 q-rows.
// K/V 128x128 half tiles double-buffered; S in regs; online softmax.
constexpr int FA_PITCH = 84;                   // words/row; 84 mod 32 = 20 -> ldsm conflict-free
constexpr int FA_TILE  = 128 * FA_PITCH;       // words per tile
constexpr size_t FA_SMEM = (size_t)4 * FA_TILE * 4;  // 2 stages x (K+V) = 172032 B

__global__ __launch_bounds__(256, 1) void flash_attn(
    const __half* __restrict__ q, const __half* __restrict__ k,
    const __half* __restrict__ vt, __half* __restrict__ ao)
{
    int qb = blockIdx.x, head = blockIdx.y;
    extern __shared__ uint32_t sm[];
    uint32_t* Ks = sm;                          // [2][FA_TILE]
    uint32_t* Vs = sm + 2 * FA_TILE;

    int tid = threadIdx.x, wid = tid >> 5, lane = tid & 31;
    int qd = lane >> 2, s = lane & 3;

    const __half* kgb = k  + (size_t)head * kSEQ * kHD;
    const __half* vgb = vt + (size_t)head * kHD * kSEQ;

    // preload Q fragments (warp's 16 q-rows), gmem -> regs, one time
    const __half* qg = q + ((size_t)head * kSEQ + qb * 128 + wid * 16) * kHD;
    uint32_t qfrag[8][4];
    #pragma unroll
    for (int kg = 0; kg < 8; kg++) {
        qfrag[kg][0] = *(const uint32_t*)(qg + (size_t)qd * kHD + kg * 16 + 2 * s);
        qfrag[kg][1] = *(const uint32_t*)(qg + (size_t)(qd + 8) * kHD + kg * 16 + 2 * s);
        qfrag[kg][2] = *(const uint32_t*)(qg + (size_t)qd * kHD + kg * 16 + 8 + 2 * s);
        qfrag[kg][3] = *(const uint32_t*)(qg + (size_t)(qd + 8) * kHD + kg * 16 + 8 + 2 * s);
    }

    auto fill = [&](int j, int st) {
        const __half* kj = kgb + (size_t)j * 128 * kHD;
        const __half* vj = vgb + j * 128;
        uint32_t* ks = Ks + st * FA_TILE;
        uint32_t* vs = Vs + st * FA_TILE;
        #pragma unroll
        for (int i = 0; i < 8; i++) {
            int u = tid + i * 256;              // 0..2047: row 0..127, 16B-unit 0..15
            int row = u >> 4, w16 = u & 15;
            int sw = row * FA_PITCH + (w16 >> 2) * 20 + (w16 & 3) * 4;
            cp16(ks + sw, kj + (size_t)row * kHD + w16 * 8);
            cp16(vs + sw, vj + (size_t)row * kSEQ + w16 * 8);
        }
    };

    float oacc[16][4] = {};
    float m0 = -3.0e38f, m1 = -3.0e38f, l0 = 0.f, l1 = 0.f;

    // ldsm per-lane B address pieces (same mapping as validated GEMM)
    int b_rsub = ((lane >> 4) * 8) + (lane & 7);
    int b_ksub = ((lane >> 3) & 1) * 4;

    fill(0, 0);
    asm volatile("cp.async.commit_group;\n");

    constexpr int NJ = kSEQ / 128;              // 20
    for (int j = 0; j < NJ; j++) {
        int st = j & 1;
        if (j + 1 < NJ) {
            fill(j + 1, st ^ 1);
            asm volatile("cp.async.commit_group;\n");
            asm volatile("cp.async.wait_group 1;\n");
        } else {
            asm volatile("cp.async.wait_group 0;\n");
        }
        __syncthreads();

        const uint32_t* ks = Ks + st * FA_TILE;
        const uint32_t* vs = Vs + st * FA_TILE;

        // ---- S = Q K^T : 16 q-rows x 128 kv per warp ----
        float sacc[16][4] = {};
        #pragma unroll
        for (int kg = 0; kg < 8; kg++) {
            int woff = (kg >> 1) * 20 + (kg & 1) * 8 + b_ksub;
            uint32_t bfr[16][2];
            #pragma unroll
            for (int tp = 0; tp < 8; tp++) {
                int row = tp * 16 + b_rsub;
                ldsm4(bfr[2 * tp][0], bfr[2 * tp][1],
                      bfr[2 * tp + 1][0], bfr[2 * tp + 1][1],
                      ks + row * FA_PITCH + woff);
            }
            #pragma unroll
            for (int tn = 0; tn < 16; tn++)
                mma_f16(sacc[tn], qfrag[kg], bfr[tn][0], bfr[tn][1]);
        }

        // ---- online softmax (rows qd -> 0-suffix, qd+8 -> 1-suffix) ----
        float mb0 = -3.0e38f, mb1 = -3.0e38f;
        #pragma unroll
        for (int tn = 0; tn < 16; tn++) {
            mb0 = fmaxf(mb0, fmaxf(sacc[tn][0], sacc[tn][1]));
            mb1 = fmaxf(mb1, fmaxf(sacc[tn][2], sacc[tn][3]));
        }
        mb0 = fmaxf(mb0, __shfl_xor_sync(0xffffffffu, mb0, 1));
        mb0 = fmaxf(mb0, __shfl_xor_sync(0xffffffffu, mb0, 2));
        mb1 = fmaxf(mb1, __shfl_xor_sync(0xffffffffu, mb1, 1));
        mb1 = fmaxf(mb1, __shfl_xor_sync(0xffffffffu, mb1, 2));
        float mn0 = fmaxf(m0, mb0), mn1 = fmaxf(m1, mb1);
        float sc0 = __expf(m0 - mn0), sc1 = __expf(m1 - mn1);
        float rs0 = 0.f, rs1 = 0.f;
        #pragma unroll
        for (int tn = 0; tn < 16; tn++) {
            sacc[tn][0] = __expf(sacc[tn][0] - mn0);
            sacc[tn][1] = __expf(sacc[tn][1] - mn0);
            sacc[tn][2] = __expf(sacc[tn][2] - mn1);
            sacc[tn][3] = __expf(sacc[tn][3] - mn1);
            rs0 += sacc[tn][0] + sacc[tn][1];
            rs1 += sacc[tn][2] + sacc[tn][3];
        }
        rs0 += __shfl_xor_sync(0xffffffffu, rs0, 1);
        rs0 += __shfl_xor_sync(0xffffffffu, rs0, 2);
        rs1 += __shfl_xor_sync(0xffffffffu, rs1, 1);
        rs1 += __shfl_xor_sync(0xffffffffu, rs1, 2);
        l0 = l0 * sc0 + rs0;
        l1 = l1 * sc1 + rs1;
        m0 = mn0; m1 = mn1;
        #pragma unroll
        for (int tn = 0; tn < 16; tn++) {
            oacc[tn][0] *= sc0; oacc[tn][1] *= sc0;
            oacc[tn][2] *= sc1; oacc[tn][3] *= sc1;
        }

        // P fragments: C-layout of S maps directly onto A-layout per k16 group
        uint32_t pfrag[8][4];
        #pragma unroll
        for (int kg = 0; kg < 8; kg++) {
            pfrag[kg][0] = pack_half2(sacc[2 * kg][0], sacc[2 * kg][1]);
            pfrag[kg][1] = pack_half2(sacc[2 * kg][2], sacc[2 * kg][3]);
            pfrag[kg][2] = pack_half2(sacc[2 * kg + 1][0], sacc[2 * kg + 1][1]);
            pfrag[kg][3] = pack_half2(sacc[2 * kg + 1][2], sacc[2 * kg + 1][3]);
        }

        // ---- O += P V : V^T tile rows = hd (n), cols = kv (k) ----
        #pragma unroll
        for (int kg = 0; kg < 8; kg++) {
            int woff = (kg >> 1) * 20 + (kg & 1) * 8 + b_ksub;
            uint32_t bfr[16][2];
            #pragma unroll
            for (int tp = 0; tp < 8; tp++) {
                int row = tp * 16 + b_rsub;
                ldsm4(bfr[2 * tp][0], bfr[2 * tp][1],
                      bfr[2 * tp + 1][0], bfr[2 * tp + 1][1],
                      vs + row * FA_PITCH + woff);
            }
            #pragma unroll
            for (int tn = 0; tn < 16; tn++)
                mma_f16(oacc[tn], pfrag[kg], bfr[tn][0], bfr[tn][1]);
        }

        __syncthreads();   // all reads of stage st done before next fill reuses it
    }

    // ---- epilogue: O / l -> ao [seq][HEADS*HD] (half) ----
    float inv0 = 1.f / l0, inv1 = 1.f / l1;
    __half* ar0 = ao + (size_t)(qb * 128 + wid * 16 + qd) * kH + head * kHD;
    __half* ar1 = ar0 + (size_t)8 * kH;
    #pragma unroll
    for (int tn = 0; tn < 16; tn++) {
        int col = tn * 8 + 2 * s;
        *(__half2*)(ar0 + col) = __floats2half2_rn(oacc[tn][0] * inv0, oacc[tn][1] * inv0);
        *(__half2*)(ar1 + col) = __floats2half2_rn(oacc[tn][2] * inv1, oacc[tn][3] * inv1);
    }
}

// ---------------- pipelined fp16 tensor-core NT GEMM (ldmatrix) ----------
constexpr int STAGES = 4;
constexpr int PITCHW = 20;
constexpr int TILE_W = 128 * PITCHW;
constexpr size_t GEMM_SMEM = (size_t)STAGES * 2 * TILE_W * 4;  // 81920

// CTA 128x128, BK=32 halves, 4 warps (2x2), warp tile 64x64, 128 threads.
template <int EPI>
__global__ __launch_bounds__(128, 2) void gemm_h(
    const __half* __restrict__ A, size_t sA,
    const __half* __restrict__ B, size_t sB,
    void* __restrict__ Cv, size_t sC, int ldc,
    int lda, int ldb,
    const float* __restrict__ bias,
    const float* __restrict__ gate,
    const float* __restrict__ res,
    int M, int N, int K)
{
    int yb = blockIdx.y * 128;
    const __half* Ag = A + (size_t)blockIdx.z * sA + (size_t)yb * lda;
    const __half* Bg = B + (size_t)blockIdx.z * sB + (size_t)(blockIdx.x * 128) * ldb;
    float* Cf = (float*)Cv + (size_t)blockIdx.z * sC;
    __half* Ch = (__half*)Cv + (size_t)blockIdx.z * sC;

    extern __shared__ uint32_t smw[];
    uint32_t* As = smw;
    uint32_t* Bs = smw + STAGES * TILE_W;

    int tid  = threadIdx.x;
    int warp = tid >> 5, lane = tid & 31;
    int wm = warp >> 1, wn = warp & 1;
    int qd = lane >> 2, s = lane & 3;

    int frow = tid >> 2;
    int fc4  = (tid & 3) * 4;

    int a_row = wm * 64 + ((lane >> 3) & 1) * 8 + (lane & 7);
    int a_kw  = (lane >> 4) * 4;
    int b_row = wn * 64 + (lane >> 4) * 8 + (lane & 7);
    int b_kw  = ((lane >> 3) & 1) * 4;

    float acc[4][8][4] = {};
    int nk = K >> 5;

    auto prefetch = [&](int k0i, int st) {
        int kbase = k0i * 32 + (tid & 3) * 8;
        uint32_t* as = As + st * TILE_W;
        uint32_t* bs = Bs + st * TILE_W;
        #pragma unroll
        for (int i = 0; i < 4; i++) {
            int row = i * 32 + frow;
            cp16(as + row * PITCHW + fc4, Ag + (size_t)row * lda + kbase);
            cp16(bs + row * PITCHW + fc4, Bg + (size_t)row * ldb + kbase);
        }
    };

    #pragma unroll
    for (int st = 0; st < STAGES - 1; st++) {
        if (st < nk) prefetch(st, st);
        asm volatile("cp.async.commit_group;\n");
    }

    for (int k0i = 0; k0i < nk; k0i++) {
        asm volatile("cp.async.wait_group %0;\n" :: "n"(STAGES - 2));
        __syncthreads();

        const uint32_t* as = As + (k0i % STAGES) * TILE_W;
        const uint32_t* bs = Bs + (k0i % STAGES) * TILE_W;
        #pragma unroll
        for (int kg = 0; kg < 2; kg++) {
            int kw = kg * 8;
            uint32_t afr[4][4];
            #pragma unroll
            for (int tm = 0; tm < 4; tm++)
                ldsm4(afr[tm][0], afr[tm][1], afr[tm][2], afr[tm][3],
                      as + (a_row + tm * 16) * PITCHW + kw + a_kw);
            uint32_t bfr[8][2];
            #pragma unroll
            for (int tp = 0; tp < 4; tp++)
                ldsm4(bfr[2 * tp][0], bfr[2 * tp][1], bfr[2 * tp + 1][0], bfr[2 * tp + 1][1],
                      bs + (b_row + tp * 16) * PITCHW + kw + b_kw);
            #pragma unroll
            for (int tn = 0; tn < 8; tn++)
                #pragma unroll
                for (int tm = 0; tm < 4; tm++)
                    mma_f16(acc[tm][tn], afr[tm], bfr[tn][0], bfr[tn][1]);
        }

        int pf = k0i + STAGES - 1;
        if (pf < nk) prefetch(pf, pf % STAGES);
        asm volatile("cp.async.commit_group;\n");
    }

    int row_base = yb + wm * 64 + qd;
    int col_base = blockIdx.x * 128 + wn * 64;
    #pragma unroll
    for (int tm = 0; tm < 4; tm++) {
        #pragma unroll
        for (int tn = 0; tn < 8; tn++) {
            int col = col_base + tn * 8 + 2 * s;
            #pragma unroll
            for (int half = 0; half < 2; half++) {
                int row = row_base + tm * 16 + half * 8;
                float v0 = acc[tm][tn][half * 2 + 0];
                float v1 = acc[tm][tn][half * 2 + 1];
                if (EPI == 0) {
                    *(__half2*)&Ch[(size_t)row * ldc + col] = __floats2half2_rn(v0, v1);
                } else if (EPI == 1) {
                    v0 = gelu_tanh(v0 + bias[col]);
                    v1 = gelu_tanh(v1 + bias[col + 1]);
                    *(__half2*)&Ch[(size_t)row * ldc + col] = __floats2half2_rn(v0, v1);
                } else {
                    if (bias) { v0 += bias[col]; v1 += bias[col + 1]; }
                    const float* rp = res + (size_t)row * ldc + col;
                    v0 = rp[0] + gate[col] * v0;
                    v1 = rp[1] + gate[col + 1] * v1;
                    *(float2*)&Cf[(size_t)row * ldc + col] = make_float2(v0, v1);
                }
            }
        }
    }
}

// ---------------- launch ----------------
extern "C" void kernel_launch(void* const* d_in, const int* in_sizes, int n_in,
                              void* d_out, int out_size) {
    const float* txt           = (const float*)d_in[0];
    const float* img           = (const float*)d_in[1];
    const float* vec           = (const float*)d_in[2];
    const float* rope          = (const float*)d_in[3];
    const float* txt_adaln_w   = (const float*)d_in[4];
    const float* txt_adaln_b   = (const float*)d_in[5];
    const float* txt_adaln_rms = (const float*)d_in[6];
    const float* img_adaln_w   = (const float*)d_in[7];
    const float* img_adaln_b   = (const float*)d_in[8];
    const float* img_adaln_rms = (const float*)d_in[9];
    const float* txt_qkv_w     = (const float*)d_in[10];
    const float* img_qkv_w     = (const float*)d_in[11];
    const float* txt_out_w     = (const float*)d_in[12];
    const float* img_out_w     = (const float*)d_in[13];
    const float* txt_norm2_w   = (const float*)d_in[14];
    const float* img_norm2_w   = (const float*)d_in[15];
    const float* txt_fc1_w     = (const float*)d_in[16];
    const float* txt_fc1_b     = (const float*)d_in[17];
    const float* txt_fc2_w     = (const float*)d_in[18];
    const float* txt_fc2_b     = (const float*)d_in[19];
    const float* img_fc1_w     = (const float*)d_in[20];
    const float* img_fc1_b     = (const float*)d_in[21];
    const float* img_fc2_w     = (const float*)d_in[22];
    const float* img_fc2_b     = (const float*)d_in[23];
    float* out = (float*)d_out;
    (void)in_sizes; (void)n_in; (void)out_size;

    static cudaStream_t s1 = nullptr;
    static cudaEvent_t ev0, ev1, ev2, ev3, ev4;
    static bool init_done = false;
    if (!init_done) {
        cudaFuncSetAttribute((const void*)gemm_h<0>, cudaFuncAttributeMaxDynamicSharedMemorySize, (int)GEMM_SMEM);
        cudaFuncSetAttribute((const void*)gemm_h<1>, cudaFuncAttributeMaxDynamicSharedMemorySize, (int)GEMM_SMEM);
        cudaFuncSetAttribute((const void*)gemm_h<2>, cudaFuncAttributeMaxDynamicSharedMemorySize, (int)GEMM_SMEM);
        cudaFuncSetAttribute((const void*)flash_attn, cudaFuncAttributeMaxDynamicSharedMemorySize, (int)FA_SMEM);
        cudaStreamCreateWithFlags(&s1, cudaStreamNonBlocking);
        cudaEventCreateWithFlags(&ev0, cudaEventDisableTiming);
        cudaEventCreateWithFlags(&ev1, cudaEventDisableTiming);
        cudaEventCreateWithFlags(&ev2, cudaEventDisableTiming);
        cudaEventCreateWithFlags(&ev3, cudaEventDisableTiming);
        cudaEventCreateWithFlags(&ev4, cudaEventDisableTiming);
        init_done = true;
    }

    float* fs = nullptr;
    __half* hs = nullptr;
    cudaGetSymbolAddress((void**)&fs, g_scratch_f);
    cudaGetSymbolAddress((void**)&hs, g_scratch_h);
    float* silu = fs + FOFF_SILU;
    float* mod  = fs + FOFF_MOD;
    float* tmod = mod;
    float* imod = mod + 6 * kH;
    float* res  = fs + FOFF_RES;
    __half* xn  = hs + HOFF_XN;
    __half* qkv = hs + HOFF_QKV;
    __half* q   = hs + HOFF_Q;
    __half* k   = hs + HOFF_K;
    __half* vt  = hs + HOFF_VT;
    __half* ao  = hs + HOFF_AO;
    __half* h1  = hs + HOFF_H1;
    __half* h1t = hs + HOFF_H1T;
    __half* wqt = hs + HOFF_WQT;
    __half* wqi = hs + HOFF_WQI;
    __half* wot = hs + HOFF_WOT;
    __half* woi = hs + HOFF_WOI;
    __half* w1t = hs + HOFF_W1T;
    __half* w1i = hs + HOFF_W1I;
    __half* w2t = hs + HOFF_W2T;
    __half* w2i = hs + HOFF_W2I;

    auto conv = [&](const float* src, __half* dst, size_t n, cudaStream_t st) {
        int n4 = (int)(n / 4);
        f2h<<<(n4 + 255) / 256, 256, 0, st>>>((const float4*)src, (__half2*)dst, n4);
    };

    // adaLN modulation (fp32, main)
    silu_kernel<<<8, 256>>>(vec, silu);
    adaln_gemv<<<(2 * 6 * kH) / 8, 256>>>(silu, txt_adaln_w, txt_adaln_b,
                                          img_adaln_w, img_adaln_b, mod);

    // ---- fork: txt qkv on s1, img qkv on main ----
    cudaEventRecord(ev0, 0);
    cudaStreamWaitEvent(s1, ev0, 0);

    conv(txt_qkv_w, wqt, (size_t)3 * kH * kH, s1);
    norm_mod<<<kL, 256, 0, s1>>>(txt, xn, txt_adaln_rms, tmod, tmod + kH);
    gemm_h<0><<<dim3(3 * kH / 128, kL / 128), 128, GEMM_SMEM, s1>>>(
        xn, 0, wqt, 0, qkv, 0, 3 * kH, kH, kH,
        nullptr, nullptr, nullptr, kL, 3 * kH, kH);
    cudaEventRecord(ev1, s1);
    conv(txt_out_w, wot, (size_t)kH * kH, s1);
    conv(img_out_w, woi, (size_t)kH * kH, s1);
    conv(txt_fc1_w, w1t, (size_t)kMLP * kH, s1);
    conv(img_fc1_w, w1i, (size_t)kMLP * kH, s1);
    conv(txt_fc2_w, w2t, (size_t)kH * kMLP, s1);
    conv(img_fc2_w, w2i, (size_t)kH * kMLP, s1);
    cudaEventRecord(ev4, s1);

    conv(img_qkv_w, wqi, (size_t)3 * kH * kH, 0);
    norm_mod<<<kN, 256>>>(img, xn + (size_t)kL * kH, img_adaln_rms, imod, imod + kH);
    gemm_h<0><<<dim3(3 * kH / 128, kN / 128), 128, GEMM_SMEM>>>(
        xn + (size_t)kL * kH, 0, wqi, 0, qkv + (size_t)kL * 3 * kH, 0, 3 * kH,
        kH, kH, nullptr, nullptr, nullptr, kN, 3 * kH, kH);
    cudaStreamWaitEvent(0, ev1, 0);

    // RoPE + head scatter
    rope_scatter<<<(kSEQ * kHEADS * 64) / 256, 256>>>(qkv, rope, q, k, vt);

    // fused joint flash attention -> ao (half)
    flash_attn<<<dim3(kSEQ / 128, kHEADS), 256, FA_SMEM>>>(q, k, vt, ao);

    // ---- fork: txt tail on s1, img tail on main ----
    cudaEventRecord(ev2, 0);
    cudaStreamWaitEvent(s1, ev2, 0);
    cudaStreamWaitEvent(0, ev4, 0);

    // txt tail
    gemm_h<2><<<dim3(kH / 128, kL / 128), 128, GEMM_SMEM, s1>>>(
        ao, 0, wot, 0, res, 0, kH, kH, kH,
        nullptr, tmod + 2 * kH, txt, kL, kH, kH);
    norm_mod<<<kL, 256, 0, s1>>>(res, xn, txt_norm2_w, tmod + 3 * kH, tmod + 4 * kH);
    gemm_h<1><<<dim3(kMLP / 128, kL / 128), 128, GEMM_SMEM, s1>>>(
        xn, 0, w1t, 0, h1t, 0, kMLP, kH, kH,
        txt_fc1_b, nullptr, nullptr, kL, kMLP, kH);
    gemm_h<2><<<dim3(kH / 128, kL / 128), 128, GEMM_SMEM, s1>>>(
        h1t, 0, w2t, 0, out, 0, kH, kMLP, kMLP,
        txt_fc2_b, tmod + 5 * kH, res, kL, kH, kMLP);
    cudaEventRecord(ev3, s1);

    // img tail
    gemm_h<2><<<dim3(kH / 128, kN / 128), 128, GEMM_SMEM>>>(
        ao + (size_t)kL * kH, 0, woi, 0, res + (size_t)kL * kH, 0, kH, kH, kH,
        nullptr, imod + 2 * kH, img, kN, kH, kH);
    norm_mod<<<kN, 256>>>(res + (size_t)kL * kH, xn + (size_t)kL * kH,
                          img_norm2_w, imod + 3 * kH, imod + 4 * kH);
    gemm_h<1><<<dim3(kMLP / 128, kN / 128), 128, GEMM_SMEM>>>(
        xn + (size_t)kL * kH, 0, w1i, 0, h1, 0, kMLP, kH, kH,
        img_fc1_b, nullptr, nullptr, kN, kMLP, kH);
    gemm_h<2><<<dim3(kH / 128, kN / 128), 128, GEMM_SMEM>>>(
        h1, 0, w2i, 0, out + (size_t)kL * kH, 0, kH, kMLP, kMLP,
        img_fc2_b, imod + 5 * kH, res + (size_t)kL * kH, kN, kH, kMLP);

    cudaStreamWaitEvent(0, ev3, 0);
}